// round 2
// baseline (speedup 1.0000x reference)
#include <cuda_runtime.h>
#include <math.h>

#define A_ 10
#define B_ 1024
#define Y_ 94
#define R_ 256
#define H_ 128
#define G_ 768
#define T_ 50
#define IN_ 350
#define FS_ 0.1f

#define BTILE 74
#define NTILES 14      // 14*74 = 1036 >= 1024
#define ROWPAD 80      // 16 ty * RT 5
#define RT 5
#define HS 257         // padded h row stride (bank-conflict free)
#define YS 96
#define DS 129

// scratch (no cudaMalloc allowed)
__device__ float  g_h[A_ * B_ * R_];   // ~10.5 MB hidden state
__device__ double g_acc[3];            // L, ep, ev

__global__ void init_kernel() {
    const size_t n = (size_t)A_ * B_ * R_;
    for (size_t i = (size_t)blockIdx.x * blockDim.x + threadIdx.x; i < n;
         i += (size_t)gridDim.x * blockDim.x)
        g_h[i] = 0.f;
    if (blockIdx.x == 0 && threadIdx.x < 3) g_acc[threadIdx.x] = 0.0;
}

// ep term is RNN-independent: fully parallel over (t, a, b)
__global__ void ep_kernel(const float* __restrict__ states) {
    int idx = blockIdx.x * blockDim.x + threadIdx.x;
    double e = 0.0;
    if (idx < T_ * A_ * B_) {
        int t = idx / (A_ * B_);
        int r = idx - t * (A_ * B_);
        int a = r >> 10;
        int b = r & 1023;
        size_t base = (((size_t)t * A_ + a) * B_ + b) * Y_ + 4 * a;
        float f0 = states[base + 0], f1 = states[base + 1];
        float f2 = states[base + 2], f3 = states[base + 3];
        size_t base1 = base + (size_t)A_ * B_ * Y_;
        float g0 = states[base1 + 0], g1 = states[base1 + 1];
        float d0 = f0 + f2 * FS_ - g0;
        float d1 = f1 + f3 * FS_ - g1;
        e = sqrt((double)d0 * d0 + (double)d1 * d1);
    }
    #pragma unroll
    for (int o = 16; o; o >>= 1) e += __shfl_down_sync(0xffffffffu, e, o);
    if ((threadIdx.x & 31) == 0) atomicAdd(&g_acc[1], e);
}

__global__ __launch_bounds__(256, 1) void step_kernel(
    const float* __restrict__ states,
    const float* __restrict__ W_ih, const float* __restrict__ W_hh,
    const float* __restrict__ b_ih, const float* __restrict__ b_hh,
    const float* __restrict__ d1w,  const float* __restrict__ d1b,
    const float* __restrict__ d2w,  const float* __restrict__ d2b,
    const float* __restrict__ mw,   const float* __restrict__ mb,
    const float* __restrict__ sw,   const float* __restrict__ sb,
    int t)
{
    extern __shared__ float sm[];
    float* h_s  = sm;                        // ROWPAD*HS
    float* y_s  = h_s + ROWPAD * HS;         // ROWPAD*YS
    float* d_s  = y_s + ROWPAD * YS;         // ROWPAD*DS
    float* e_s  = d_s + ROWPAD * DS;         // ROWPAD*DS
    float* ms_s = e_s + ROWPAD * DS;         // ROWPAD*4

    const int a     = blockIdx.y;
    const int row0  = blockIdx.x * BTILE;
    const int nrows = min(BTILE, B_ - row0);
    const int tid   = threadIdx.x;
    const int tx    = tid & 15;
    const int ty    = tid >> 4;

    // ---- stage h and y_t into smem (zero-fill pad rows: no NaN garbage) ----
    const float* hg = g_h + ((size_t)a * B_ + row0) * R_;
    for (int i = tid; i < ROWPAD * R_; i += 256) {
        int r = i >> 8, k = i & 255;
        h_s[r * HS + k] = (r < nrows) ? hg[(size_t)r * R_ + k] : 0.f;
    }
    const float* yg = states + (((size_t)t * A_ + a) * B_ + row0) * Y_;
    for (int i = tid; i < ROWPAD * Y_; i += 256) {
        int r = i / Y_, k = i - r * Y_;
        y_s[r * YS + k] = (r < nrows) ? yg[(size_t)r * Y_ + k] : 0.f;
    }
    __syncthreads();

    // ---- D1: d = relu(d1_w @ h + d1_b), rows=ty+16i, cols=tx+16jj ----
    {
        float acc[RT][8];
        #pragma unroll
        for (int jj = 0; jj < 8; jj++) {
            float bv = d1b[a * H_ + tx + 16 * jj];
            #pragma unroll
            for (int i = 0; i < RT; i++) acc[i][jj] = bv;
        }
        const float* W = d1w + (size_t)a * H_ * R_;
        for (int k = 0; k < R_; k++) {
            float hv[RT];
            #pragma unroll
            for (int i = 0; i < RT; i++) hv[i] = h_s[(ty + 16 * i) * HS + k];
            #pragma unroll
            for (int jj = 0; jj < 8; jj++) {
                float wv = W[(size_t)(tx + 16 * jj) * R_ + k];
                #pragma unroll
                for (int i = 0; i < RT; i++) acc[i][jj] += hv[i] * wv;
            }
        }
        #pragma unroll
        for (int i = 0; i < RT; i++)
            #pragma unroll
            for (int jj = 0; jj < 8; jj++)
                d_s[(ty + 16 * i) * DS + tx + 16 * jj] = fmaxf(acc[i][jj], 0.f);
    }
    __syncthreads();

    // ---- D2: d = relu(d2_w @ d + d2_b) ----
    {
        float acc[RT][8];
        #pragma unroll
        for (int jj = 0; jj < 8; jj++) {
            float bv = d2b[a * H_ + tx + 16 * jj];
            #pragma unroll
            for (int i = 0; i < RT; i++) acc[i][jj] = bv;
        }
        const float* W = d2w + (size_t)a * H_ * H_;
        for (int k = 0; k < H_; k++) {
            float dv[RT];
            #pragma unroll
            for (int i = 0; i < RT; i++) dv[i] = d_s[(ty + 16 * i) * DS + k];
            #pragma unroll
            for (int jj = 0; jj < 8; jj++) {
                float wv = W[(size_t)(tx + 16 * jj) * H_ + k];
                #pragma unroll
                for (int i = 0; i < RT; i++) acc[i][jj] += dv[i] * wv;
            }
        }
        #pragma unroll
        for (int i = 0; i < RT; i++)
            #pragma unroll
            for (int jj = 0; jj < 8; jj++)
                e_s[(ty + 16 * i) * DS + tx + 16 * jj] = fmaxf(acc[i][jj], 0.f);
    }
    __syncthreads();

    // ---- mean / std heads (4 dots of K=128 per row) ----
    for (int task = tid; task < nrows * 4; task += 256) {
        int r = task >> 2, o = task & 3;
        const float* W = (o < 2) ? (mw + ((size_t)a * 2 + o) * H_)
                                 : (sw + ((size_t)a * 2 + (o - 2)) * H_);
        float acc = (o < 2) ? mb[a * 2 + o] : sb[a * 2 + o - 2];
        for (int k = 0; k < H_; k++) acc += e_s[r * DS + k] * W[k];
        if (o >= 2)  // softplus
            acc = fmaxf(acc, 0.f) + log1pf(expf(-fabsf(acc)));
        ms_s[r * 4 + o] = acc;
    }
    __syncthreads();

    // ---- per-row NLL + ev accumulation ----
    {
        double lsum = 0.0, esum = 0.0;
        if (tid < nrows) {
            int b = row0 + tid;
            size_t xb = (((size_t)(t + 1) * A_ + a) * B_ + b) * Y_ + 4 * a;
            float x0 = states[xb + 2], x1 = states[xb + 3];
            float m0 = ms_s[tid * 4 + 0], m1 = ms_s[tid * 4 + 1];
            float s0 = ms_s[tid * 4 + 2], s1 = ms_s[tid * 4 + 3];
            float z0 = (x0 - m0) / s0, z1 = (x1 - m1) / s1;
            const double L2PI = 1.8378770664093453;
            lsum = 0.5 * ((double)(z0 * z0) + (double)(z1 * z1)
                 + 2.0 * ((double)logf(s0) + (double)logf(s1)) + 2.0 * L2PI);
            float dm0 = m0 - x0, dm1 = m1 - x1;
            esum = sqrt((double)dm0 * dm0 + (double)dm1 * dm1);
        }
        #pragma unroll
        for (int o = 16; o; o >>= 1) {
            lsum += __shfl_down_sync(0xffffffffu, lsum, o);
            esum += __shfl_down_sync(0xffffffffu, esum, o);
        }
        if ((tid & 31) == 0) {
            atomicAdd(&g_acc[0], lsum);
            atomicAdd(&g_acc[2], esum);
        }
    }

    // ---- GRU: gi = W_ih @ [y;h] + b_ih, gh = W_hh @ h + b_hh, update h ----
    const float* Wi = W_ih + (size_t)a * G_ * IN_;
    const float* Wh = W_hh + (size_t)a * G_ * R_;
    for (int jc = 0; jc < 8; jc++) {
        int j0 = jc * 32 + tx;
        float air[RT][2], aiz[RT][2], ain[RT][2];
        float ahr[RT][2], ahz[RT][2], ahn[RT][2];
        #pragma unroll
        for (int jj = 0; jj < 2; jj++) {
            int j = j0 + 16 * jj;
            float bir = b_ih[a * G_ + j];
            float biz = b_ih[a * G_ + 256 + j];
            float bin = b_ih[a * G_ + 512 + j];
            float bhr = b_hh[a * G_ + j];
            float bhz = b_hh[a * G_ + 256 + j];
            float bhn = b_hh[a * G_ + 512 + j];
            #pragma unroll
            for (int i = 0; i < RT; i++) {
                air[i][jj] = bir; aiz[i][jj] = biz; ain[i][jj] = bin;
                ahr[i][jj] = bhr; ahz[i][jj] = bhz; ahn[i][jj] = bhn;
            }
        }
        // y contribution (K = 94)
        for (int k = 0; k < Y_; k++) {
            float yv[RT];
            #pragma unroll
            for (int i = 0; i < RT; i++) yv[i] = y_s[(ty + 16 * i) * YS + k];
            #pragma unroll
            for (int jj = 0; jj < 2; jj++) {
                int j = j0 + 16 * jj;
                float wr = Wi[(size_t)j * IN_ + k];
                float wz = Wi[(size_t)(256 + j) * IN_ + k];
                float wn = Wi[(size_t)(512 + j) * IN_ + k];
                #pragma unroll
                for (int i = 0; i < RT; i++) {
                    air[i][jj] += yv[i] * wr;
                    aiz[i][jj] += yv[i] * wz;
                    ain[i][jj] += yv[i] * wn;
                }
            }
        }
        // h contribution (K = 256) into both gi and gh
        for (int k = 0; k < R_; k++) {
            float hv[RT];
            #pragma unroll
            for (int i = 0; i < RT; i++) hv[i] = h_s[(ty + 16 * i) * HS + k];
            #pragma unroll
            for (int jj = 0; jj < 2; jj++) {
                int j = j0 + 16 * jj;
                float wir = Wi[(size_t)j * IN_ + Y_ + k];
                float wiz = Wi[(size_t)(256 + j) * IN_ + Y_ + k];
                float win = Wi[(size_t)(512 + j) * IN_ + Y_ + k];
                float whr = Wh[(size_t)j * R_ + k];
                float whz = Wh[(size_t)(256 + j) * R_ + k];
                float whn = Wh[(size_t)(512 + j) * R_ + k];
                #pragma unroll
                for (int i = 0; i < RT; i++) {
                    air[i][jj] += hv[i] * wir;
                    aiz[i][jj] += hv[i] * wiz;
                    ain[i][jj] += hv[i] * win;
                    ahr[i][jj] += hv[i] * whr;
                    ahz[i][jj] += hv[i] * whz;
                    ahn[i][jj] += hv[i] * whn;
                }
            }
        }
        // gate combine + in-place h update (block owns these rows exclusively)
        #pragma unroll
        for (int i = 0; i < RT; i++) {
            int r = ty + 16 * i;
            if (r < nrows) {
                #pragma unroll
                for (int jj = 0; jj < 2; jj++) {
                    int j = j0 + 16 * jj;
                    float rg = 1.f / (1.f + expf(-(air[i][jj] + ahr[i][jj])));
                    float zg = 1.f / (1.f + expf(-(aiz[i][jj] + ahz[i][jj])));
                    float ng = tanhf(ain[i][jj] + rg * ahn[i][jj]);
                    float hold = h_s[r * HS + j];
                    float hnew = (1.f - zg) * ng + zg * hold;
                    g_h[((size_t)a * B_ + row0 + r) * R_ + j] = hnew;
                }
            }
        }
    }
}

__global__ void final_kernel(float* out) {
    if (threadIdx.x == 0) {
        const double denom = (double)T_ * A_;
        out[0] = (float)(g_acc[0] / denom);
        out[1] = (float)(g_acc[1] / denom);
        out[2] = (float)(g_acc[2] / denom);
    }
}

extern "C" void kernel_launch(void* const* d_in, const int* in_sizes, int n_in,
                              void* d_out, int out_size) {
    const float* states = (const float*)d_in[0];
    const float* W_ih   = (const float*)d_in[1];
    const float* W_hh   = (const float*)d_in[2];
    const float* b_ih   = (const float*)d_in[3];
    const float* b_hh   = (const float*)d_in[4];
    const float* d1w    = (const float*)d_in[5];
    const float* d1b    = (const float*)d_in[6];
    const float* d2w    = (const float*)d_in[7];
    const float* d2b    = (const float*)d_in[8];
    const float* mw     = (const float*)d_in[9];
    const float* mb     = (const float*)d_in[10];
    const float* sw     = (const float*)d_in[11];
    const float* sb     = (const float*)d_in[12];
    float* out = (float*)d_out;

    const size_t SMEM = (size_t)ROWPAD * (HS + YS + DS + DS + 4) * sizeof(float); // 196,800 B
    cudaFuncSetAttribute(step_kernel, cudaFuncAttributeMaxDynamicSharedMemorySize, (int)SMEM);

    init_kernel<<<256, 256>>>();
    ep_kernel<<<(T_ * A_ * B_ + 255) / 256, 256>>>(states);

    dim3 grid(NTILES, A_);
    for (int t = 0; t < T_; t++) {
        step_kernel<<<grid, 256, SMEM>>>(states, W_ih, W_hh, b_ih, b_hh,
                                         d1w, d1b, d2w, d2b, mw, mb, sw, sb, t);
    }
    final_kernel<<<1, 32>>>(out);
}

// round 3
// speedup vs baseline: 1.3383x; 1.3383x over previous
#include <cuda_runtime.h>
#include <math.h>

#define A_ 10
#define B_ 1024
#define Y_ 94
#define R_ 256
#define H_ 128
#define G_ 768
#define T_ 50
#define IN_ 350
#define INP_ 352     // padded [y(94)+2 zeros | h(256)] row length for packed W_ih
#define FS_ 0.1f

#define BTILE 74
#define NTILES 14      // 14*74 = 1036 >= 1024
#define ROWPAD 80      // 16 ty * RT 5
#define RT 5
#define NTHREADS 512
#define ES 356         // enc row stride (float4-aligned)
#define DS 132         // d/e row stride (float4-aligned)

// scratch (no cudaMalloc allowed)
__device__ float  g_h[A_ * B_ * R_];          // hidden state
__device__ float  g_Wip[A_ * G_ * INP_];      // packed W_ih, 10.8 MB
__device__ double g_acc[3];                   // L, ep, ev

__global__ void init_kernel() {
    const size_t n = (size_t)A_ * B_ * R_;
    for (size_t i = (size_t)blockIdx.x * blockDim.x + threadIdx.x; i < n;
         i += (size_t)gridDim.x * blockDim.x)
        g_h[i] = 0.f;
    if (blockIdx.x == 0 && threadIdx.x < 3) g_acc[threadIdx.x] = 0.0;
}

// Repack W_ih [A,768,350] -> [A,768,352]: cols 0..93 = y-weights, 94..95 = 0,
// 96..351 = h-weights. Makes every GEMM operand 16B-aligned.
__global__ void pack_wi_kernel(const float* __restrict__ W_ih) {
    const int n = A_ * G_ * INP_;
    for (int i = blockIdx.x * blockDim.x + threadIdx.x; i < n;
         i += gridDim.x * blockDim.x) {
        int k = i % INP_;
        int row = i / INP_;          // a*G_ + j
        float v = 0.f;
        if (k < Y_)       v = W_ih[(size_t)row * IN_ + k];
        else if (k >= 96) v = W_ih[(size_t)row * IN_ + (k - 2)];
        g_Wip[i] = v;
    }
}

// ep term is RNN-independent: fully parallel over (t, a, b)
__global__ void ep_kernel(const float* __restrict__ states) {
    int idx = blockIdx.x * blockDim.x + threadIdx.x;
    double e = 0.0;
    if (idx < T_ * A_ * B_) {
        int t = idx / (A_ * B_);
        int r = idx - t * (A_ * B_);
        int a = r >> 10;
        int b = r & 1023;
        size_t base = (((size_t)t * A_ + a) * B_ + b) * Y_ + 4 * a;
        float f0 = states[base + 0], f1 = states[base + 1];
        float f2 = states[base + 2], f3 = states[base + 3];
        size_t base1 = base + (size_t)A_ * B_ * Y_;
        float g0 = states[base1 + 0], g1 = states[base1 + 1];
        float d0 = f0 + f2 * FS_ - g0;
        float d1 = f1 + f3 * FS_ - g1;
        e = sqrt((double)d0 * d0 + (double)d1 * d1);
    }
    #pragma unroll
    for (int o = 16; o; o >>= 1) e += __shfl_down_sync(0xffffffffu, e, o);
    if ((threadIdx.x & 31) == 0) atomicAdd(&g_acc[1], e);
}

__global__ __launch_bounds__(NTHREADS) void step_kernel(
    const float* __restrict__ states,
    const float* __restrict__ W_hh,
    const float* __restrict__ b_ih, const float* __restrict__ b_hh,
    const float* __restrict__ d1w,  const float* __restrict__ d1b,
    const float* __restrict__ d2w,  const float* __restrict__ d2b,
    const float* __restrict__ mw,   const float* __restrict__ mb,
    const float* __restrict__ sw,   const float* __restrict__ sb,
    int t)
{
    extern __shared__ float sm[];
    float* enc_s = sm;                         // ROWPAD*ES  [y(96 padded)|h(256)]
    float* d_s   = enc_s + ROWPAD * ES;        // ROWPAD*DS
    float* e_s   = d_s   + ROWPAD * DS;        // ROWPAD*DS
    float* ms_s  = e_s   + ROWPAD * DS;        // ROWPAD*4

    const int a     = blockIdx.y;
    const int row0  = blockIdx.x * BTILE;
    const int nrows = min(BTILE, B_ - row0);
    const int tid   = threadIdx.x;
    const int tx    = tid & 31;     // lane (gemm column)
    const int ty    = tid >> 5;     // warp (row-group) -> smem reads broadcast

    // ---- stage enc = [y | 0 0 | h] into smem, zero-pad tail rows ----
    const float* hg = g_h + ((size_t)a * B_ + row0) * R_;
    for (int i = tid; i < ROWPAD * R_; i += NTHREADS) {
        int r = i >> 8, k = i & 255;
        enc_s[r * ES + 96 + k] = (r < nrows) ? hg[(size_t)r * R_ + k] : 0.f;
    }
    const float* yg = states + (((size_t)t * A_ + a) * B_ + row0) * Y_;
    for (int i = tid; i < ROWPAD * 96; i += NTHREADS) {
        int r = i / 96, k = i - r * 96;
        enc_s[r * ES + k] = (r < nrows && k < Y_) ? yg[(size_t)r * Y_ + k] : 0.f;
    }
    __syncthreads();

    // ---- D1: d = relu(d1_w @ h + d1_b), cols j = tx + 32*jj (jj<4) ----
    {
        float acc[RT][4];
        #pragma unroll
        for (int jj = 0; jj < 4; jj++) {
            float bv = d1b[a * H_ + tx + 32 * jj];
            #pragma unroll
            for (int i = 0; i < RT; i++) acc[i][jj] = bv;
        }
        const float* W = d1w + (size_t)a * H_ * R_;
        for (int k = 0; k < R_; k += 4) {
            float4 hv[RT];
            #pragma unroll
            for (int i = 0; i < RT; i++)
                hv[i] = *reinterpret_cast<const float4*>(&enc_s[(ty + 16 * i) * ES + 96 + k]);
            #pragma unroll
            for (int jj = 0; jj < 4; jj++) {
                float4 wv = *reinterpret_cast<const float4*>(&W[(size_t)(tx + 32 * jj) * R_ + k]);
                #pragma unroll
                for (int i = 0; i < RT; i++) {
                    acc[i][jj] += hv[i].x * wv.x + hv[i].y * wv.y
                                + hv[i].z * wv.z + hv[i].w * wv.w;
                }
            }
        }
        #pragma unroll
        for (int i = 0; i < RT; i++)
            #pragma unroll
            for (int jj = 0; jj < 4; jj++)
                d_s[(ty + 16 * i) * DS + tx + 32 * jj] = fmaxf(acc[i][jj], 0.f);
    }
    __syncthreads();

    // ---- D2: e = relu(d2_w @ d + d2_b) ----
    {
        float acc[RT][4];
        #pragma unroll
        for (int jj = 0; jj < 4; jj++) {
            float bv = d2b[a * H_ + tx + 32 * jj];
            #pragma unroll
            for (int i = 0; i < RT; i++) acc[i][jj] = bv;
        }
        const float* W = d2w + (size_t)a * H_ * H_;
        for (int k = 0; k < H_; k += 4) {
            float4 dv[RT];
            #pragma unroll
            for (int i = 0; i < RT; i++)
                dv[i] = *reinterpret_cast<const float4*>(&d_s[(ty + 16 * i) * DS + k]);
            #pragma unroll
            for (int jj = 0; jj < 4; jj++) {
                float4 wv = *reinterpret_cast<const float4*>(&W[(size_t)(tx + 32 * jj) * H_ + k]);
                #pragma unroll
                for (int i = 0; i < RT; i++) {
                    acc[i][jj] += dv[i].x * wv.x + dv[i].y * wv.y
                                + dv[i].z * wv.z + dv[i].w * wv.w;
                }
            }
        }
        #pragma unroll
        for (int i = 0; i < RT; i++)
            #pragma unroll
            for (int jj = 0; jj < 4; jj++)
                e_s[(ty + 16 * i) * DS + tx + 32 * jj] = fmaxf(acc[i][jj], 0.f);
    }
    __syncthreads();

    // ---- mean / std heads ----
    for (int task = tid; task < nrows * 4; task += NTHREADS) {
        int r = task >> 2, o = task & 3;
        const float* W = (o < 2) ? (mw + ((size_t)a * 2 + o) * H_)
                                 : (sw + ((size_t)a * 2 + (o - 2)) * H_);
        float acc = (o < 2) ? mb[a * 2 + o] : sb[a * 2 + o - 2];
        for (int k = 0; k < H_; k++) acc += e_s[r * DS + k] * W[k];
        if (o >= 2)
            acc = fmaxf(acc, 0.f) + log1pf(expf(-fabsf(acc)));
        ms_s[r * 4 + o] = acc;
    }
    __syncthreads();

    // ---- per-row NLL + ev ----
    {
        double lsum = 0.0, esum = 0.0;
        if (tid < nrows) {
            int b = row0 + tid;
            size_t xb = (((size_t)(t + 1) * A_ + a) * B_ + b) * Y_ + 4 * a;
            float x0 = states[xb + 2], x1 = states[xb + 3];
            float m0 = ms_s[tid * 4 + 0], m1 = ms_s[tid * 4 + 1];
            float s0 = ms_s[tid * 4 + 2], s1 = ms_s[tid * 4 + 3];
            float z0 = (x0 - m0) / s0, z1 = (x1 - m1) / s1;
            const double L2PI = 1.8378770664093453;
            lsum = 0.5 * ((double)(z0 * z0) + (double)(z1 * z1)
                 + 2.0 * ((double)logf(s0) + (double)logf(s1)) + 2.0 * L2PI);
            float dm0 = m0 - x0, dm1 = m1 - x1;
            esum = sqrt((double)dm0 * dm0 + (double)dm1 * dm1);
        }
        #pragma unroll
        for (int o = 16; o; o >>= 1) {
            lsum += __shfl_down_sync(0xffffffffu, lsum, o);
            esum += __shfl_down_sync(0xffffffffu, esum, o);
        }
        if ((tid & 31) == 0) {
            atomicAdd(&g_acc[0], lsum);
            atomicAdd(&g_acc[2], esum);
        }
    }

    // ---- GRU ----
    const float* Wip = g_Wip + (size_t)a * G_ * INP_;
    const float* Wh  = W_hh  + (size_t)a * G_ * R_;
    for (int jc = 0; jc < 4; jc++) {
        const int j0 = jc * 64 + tx;   // gate cols j0, j0+32
        float air[RT][2], aiz[RT][2], ain[RT][2];
        float ahr[RT][2], ahz[RT][2], ahn[RT][2];
        #pragma unroll
        for (int jj = 0; jj < 2; jj++) {
            int j = j0 + 32 * jj;
            float bir = b_ih[a * G_ + j];
            float biz = b_ih[a * G_ + 256 + j];
            float bin = b_ih[a * G_ + 512 + j];
            float bhr = b_hh[a * G_ + j];
            float bhz = b_hh[a * G_ + 256 + j];
            float bhn = b_hh[a * G_ + 512 + j];
            #pragma unroll
            for (int i = 0; i < RT; i++) {
                air[i][jj] = bir; aiz[i][jj] = biz; ain[i][jj] = bin;
                ahr[i][jj] = bhr; ahz[i][jj] = bhz; ahn[i][jj] = bhn;
            }
        }

        // gi over unified enc (K = 352, padded zeros make it exact)
        for (int k = 0; k < INP_; k += 4) {
            float4 hv[RT];
            #pragma unroll
            for (int i = 0; i < RT; i++)
                hv[i] = *reinterpret_cast<const float4*>(&enc_s[(ty + 16 * i) * ES + k]);
            #pragma unroll
            for (int jj = 0; jj < 2; jj++) {
                int j = j0 + 32 * jj;
                float4 wr = *reinterpret_cast<const float4*>(&Wip[(size_t)j * INP_ + k]);
                float4 wz = *reinterpret_cast<const float4*>(&Wip[(size_t)(256 + j) * INP_ + k]);
                float4 wn = *reinterpret_cast<const float4*>(&Wip[(size_t)(512 + j) * INP_ + k]);
                #pragma unroll
                for (int i = 0; i < RT; i++) {
                    air[i][jj] += hv[i].x * wr.x + hv[i].y * wr.y + hv[i].z * wr.z + hv[i].w * wr.w;
                    aiz[i][jj] += hv[i].x * wz.x + hv[i].y * wz.y + hv[i].z * wz.z + hv[i].w * wz.w;
                    ain[i][jj] += hv[i].x * wn.x + hv[i].y * wn.y + hv[i].z * wn.z + hv[i].w * wn.w;
                }
            }
        }
        // gh over h (K = 256)
        for (int k = 0; k < R_; k += 4) {
            float4 hv[RT];
            #pragma unroll
            for (int i = 0; i < RT; i++)
                hv[i] = *reinterpret_cast<const float4*>(&enc_s[(ty + 16 * i) * ES + 96 + k]);
            #pragma unroll
            for (int jj = 0; jj < 2; jj++) {
                int j = j0 + 32 * jj;
                float4 wr = *reinterpret_cast<const float4*>(&Wh[(size_t)j * R_ + k]);
                float4 wz = *reinterpret_cast<const float4*>(&Wh[(size_t)(256 + j) * R_ + k]);
                float4 wn = *reinterpret_cast<const float4*>(&Wh[(size_t)(512 + j) * R_ + k]);
                #pragma unroll
                for (int i = 0; i < RT; i++) {
                    ahr[i][jj] += hv[i].x * wr.x + hv[i].y * wr.y + hv[i].z * wr.z + hv[i].w * wr.w;
                    ahz[i][jj] += hv[i].x * wz.x + hv[i].y * wz.y + hv[i].z * wz.z + hv[i].w * wz.w;
                    ahn[i][jj] += hv[i].x * wn.x + hv[i].y * wn.y + hv[i].z * wn.z + hv[i].w * wn.w;
                }
            }
        }
        // combine + in-place h update
        #pragma unroll
        for (int i = 0; i < RT; i++) {
            int r = ty + 16 * i;
            if (r < nrows) {
                #pragma unroll
                for (int jj = 0; jj < 2; jj++) {
                    int j = j0 + 32 * jj;
                    float rg = 1.f / (1.f + expf(-(air[i][jj] + ahr[i][jj])));
                    float zg = 1.f / (1.f + expf(-(aiz[i][jj] + ahz[i][jj])));
                    float ng = tanhf(ain[i][jj] + rg * ahn[i][jj]);
                    float hold = enc_s[r * ES + 96 + j];
                    float hnew = (1.f - zg) * ng + zg * hold;
                    g_h[((size_t)a * B_ + row0 + r) * R_ + j] = hnew;
                }
            }
        }
    }
}

__global__ void final_kernel(float* out) {
    if (threadIdx.x == 0) {
        const double denom = (double)T_ * A_;
        out[0] = (float)(g_acc[0] / denom);
        out[1] = (float)(g_acc[1] / denom);
        out[2] = (float)(g_acc[2] / denom);
    }
}

extern "C" void kernel_launch(void* const* d_in, const int* in_sizes, int n_in,
                              void* d_out, int out_size) {
    const float* states = (const float*)d_in[0];
    const float* W_ih   = (const float*)d_in[1];
    const float* W_hh   = (const float*)d_in[2];
    const float* b_ih   = (const float*)d_in[3];
    const float* b_hh   = (const float*)d_in[4];
    const float* d1w    = (const float*)d_in[5];
    const float* d1b    = (const float*)d_in[6];
    const float* d2w    = (const float*)d_in[7];
    const float* d2b    = (const float*)d_in[8];
    const float* mw     = (const float*)d_in[9];
    const float* mb     = (const float*)d_in[10];
    const float* sw     = (const float*)d_in[11];
    const float* sb     = (const float*)d_in[12];
    float* out = (float*)d_out;

    const size_t SMEM = (size_t)ROWPAD * (ES + DS + DS + 4) * sizeof(float); // 199,680 B
    cudaFuncSetAttribute(step_kernel, cudaFuncAttributeMaxDynamicSharedMemorySize, (int)SMEM);

    init_kernel<<<256, 256>>>();
    pack_wi_kernel<<<512, 256>>>(W_ih);
    ep_kernel<<<(T_ * A_ * B_ + 255) / 256, 256>>>(states);

    dim3 grid(NTILES, A_);
    for (int t = 0; t < T_; t++) {
        step_kernel<<<grid, NTHREADS, SMEM>>>(states, W_hh, b_ih, b_hh,
                                              d1w, d1b, d2w, d2b, mw, mb, sw, sb, t);
    }
    final_kernel<<<1, 32>>>(out);
}

// round 4
// speedup vs baseline: 3.4336x; 2.5657x over previous
#include <cuda_runtime.h>
#include <math.h>

#define A_ 10
#define B_ 1024
#define Y_ 94
#define R_ 256
#define H_ 128
#define G_ 768
#define T_ 50
#define IN_ 350
#define INP_ 352     // padded [y(94)+2 zeros | h(256)]
#define FS_ 0.1f

#define BTILE 74
#define NTILES 14      // 14*74 = 1036 >= 1024
#define ROWPAD 80      // 16 warps * RT 5
#define RT 5
#define NTHREADS 512
#define ES 356         // enc row stride (float4-aligned)
#define DS 132         // d/e row stride (float4-aligned)

// scratch (no cudaMalloc allowed)
__device__ float  g_h[A_ * B_ * R_];          // hidden state
__device__ float  g_WiT[A_ * INP_ * G_];      // W_ih packed+transposed [a][k][j]
__device__ float  g_WhT[A_ * R_ * G_];        // W_hh transposed [a][k][j]
__device__ float  g_d1T[A_ * R_ * H_];        // d1_w transposed [a][k][j]
__device__ float  g_d2T[A_ * H_ * H_];        // d2_w transposed [a][k][j]
__device__ double g_acc[3];                   // L, ep, ev

__global__ void init_kernel() {
    const size_t n = (size_t)A_ * B_ * R_;
    for (size_t i = (size_t)blockIdx.x * blockDim.x + threadIdx.x; i < n;
         i += (size_t)gridDim.x * blockDim.x)
        g_h[i] = 0.f;
    if (blockIdx.x == 0 && threadIdx.x < 3) g_acc[threadIdx.x] = 0.0;
}

// ---- one-time weight transposes (j-contiguous => coalesced LDG in steps) ----
__global__ void pack_wi_kernel(const float* __restrict__ W_ih) {
    const int n = A_ * INP_ * G_;
    for (int i = blockIdx.x * blockDim.x + threadIdx.x; i < n;
         i += gridDim.x * blockDim.x) {
        int j = i % G_;
        int r = i / G_;
        int k = r % INP_;
        int a = r / INP_;
        float v = 0.f;
        if (k < Y_)       v = W_ih[((size_t)a * G_ + j) * IN_ + k];
        else if (k >= 96) v = W_ih[((size_t)a * G_ + j) * IN_ + (k - 2)];
        g_WiT[i] = v;
    }
}
__global__ void pack_wh_kernel(const float* __restrict__ W_hh) {
    const int n = A_ * R_ * G_;
    for (int i = blockIdx.x * blockDim.x + threadIdx.x; i < n;
         i += gridDim.x * blockDim.x) {
        int j = i % G_;
        int r = i / G_;
        int k = r % R_;
        int a = r / R_;
        g_WhT[i] = W_hh[((size_t)a * G_ + j) * R_ + k];
    }
}
__global__ void pack_d_kernel(const float* __restrict__ d1w,
                              const float* __restrict__ d2w) {
    const int n1 = A_ * R_ * H_;
    for (int i = blockIdx.x * blockDim.x + threadIdx.x; i < n1;
         i += gridDim.x * blockDim.x) {
        int j = i % H_;
        int r = i / H_;
        int k = r % R_;
        int a = r / R_;
        g_d1T[i] = d1w[((size_t)a * H_ + j) * R_ + k];
    }
    const int n2 = A_ * H_ * H_;
    for (int i = blockIdx.x * blockDim.x + threadIdx.x; i < n2;
         i += gridDim.x * blockDim.x) {
        int j = i % H_;
        int r = i / H_;
        int k = r % H_;
        int a = r / H_;
        g_d2T[i] = d2w[((size_t)a * H_ + j) * H_ + k];
    }
}

// ep term is RNN-independent: fully parallel over (t, a, b)
__global__ void ep_kernel(const float* __restrict__ states) {
    int idx = blockIdx.x * blockDim.x + threadIdx.x;
    double e = 0.0;
    if (idx < T_ * A_ * B_) {
        int t = idx / (A_ * B_);
        int r = idx - t * (A_ * B_);
        int a = r >> 10;
        int b = r & 1023;
        size_t base = (((size_t)t * A_ + a) * B_ + b) * Y_ + 4 * a;
        float f0 = states[base + 0], f1 = states[base + 1];
        float f2 = states[base + 2], f3 = states[base + 3];
        size_t base1 = base + (size_t)A_ * B_ * Y_;
        float g0 = states[base1 + 0], g1 = states[base1 + 1];
        float d0 = f0 + f2 * FS_ - g0;
        float d1 = f1 + f3 * FS_ - g1;
        e = sqrt((double)d0 * d0 + (double)d1 * d1);
    }
    #pragma unroll
    for (int o = 16; o; o >>= 1) e += __shfl_down_sync(0xffffffffu, e, o);
    if ((threadIdx.x & 31) == 0) atomicAdd(&g_acc[1], e);
}

__global__ __launch_bounds__(NTHREADS) void step_kernel(
    const float* __restrict__ states,
    const float* __restrict__ b_ih, const float* __restrict__ b_hh,
    const float* __restrict__ d1b,  const float* __restrict__ d2b,
    const float* __restrict__ mw,   const float* __restrict__ mb,
    const float* __restrict__ sw,   const float* __restrict__ sb,
    int t)
{
    extern __shared__ float sm[];
    float* enc_s = sm;                         // ROWPAD*ES  [y(96 padded)|h(256)]
    float* d_s   = enc_s + ROWPAD * ES;        // ROWPAD*DS
    float* e_s   = d_s   + ROWPAD * DS;        // ROWPAD*DS
    float* ms_s  = e_s   + ROWPAD * DS;        // ROWPAD*4

    const int a     = blockIdx.y;
    const int row0  = blockIdx.x * BTILE;
    const int nrows = min(BTILE, B_ - row0);
    const int tid   = threadIdx.x;
    const int tx    = tid & 31;     // lane -> gemm column (contiguous across lanes)
    const int ty    = tid >> 5;     // warp -> row-group (smem reads broadcast)

    // ---- stage enc = [y | 0 0 | h] into smem, zero-pad tail rows ----
    const float* hg = g_h + ((size_t)a * B_ + row0) * R_;
    for (int i = tid; i < ROWPAD * R_; i += NTHREADS) {
        int r = i >> 8, k = i & 255;
        enc_s[r * ES + 96 + k] = (r < nrows) ? hg[(size_t)r * R_ + k] : 0.f;
    }
    const float* yg = states + (((size_t)t * A_ + a) * B_ + row0) * Y_;
    for (int i = tid; i < ROWPAD * 96; i += NTHREADS) {
        int r = i / 96, k = i - r * 96;
        enc_s[r * ES + k] = (r < nrows && k < Y_) ? yg[(size_t)r * Y_ + k] : 0.f;
    }
    __syncthreads();

    // ---- D1: d = relu(d1_wT^T h + d1_b), cols j = tx + 32*jj ----
    {
        float acc[RT][4];
        #pragma unroll
        for (int jj = 0; jj < 4; jj++) {
            float bv = d1b[a * H_ + tx + 32 * jj];
            #pragma unroll
            for (int i = 0; i < RT; i++) acc[i][jj] = bv;
        }
        const float* W = g_d1T + (size_t)a * R_ * H_;
        for (int k = 0; k < R_; k += 4) {
            float4 hv[RT];
            #pragma unroll
            for (int i = 0; i < RT; i++)
                hv[i] = *reinterpret_cast<const float4*>(&enc_s[(ty + 16 * i) * ES + 96 + k]);
            #pragma unroll
            for (int kk = 0; kk < 4; kk++) {
                const float* Wr = W + (size_t)(k + kk) * H_;
                #pragma unroll
                for (int jj = 0; jj < 4; jj++) {
                    float wv = Wr[tx + 32 * jj];
                    #pragma unroll
                    for (int i = 0; i < RT; i++)
                        acc[i][jj] += reinterpret_cast<const float*>(&hv[i])[kk] * wv;
                }
            }
        }
        #pragma unroll
        for (int i = 0; i < RT; i++)
            #pragma unroll
            for (int jj = 0; jj < 4; jj++)
                d_s[(ty + 16 * i) * DS + tx + 32 * jj] = fmaxf(acc[i][jj], 0.f);
    }
    __syncthreads();

    // ---- D2: e = relu(d2_wT^T d + d2_b) ----
    {
        float acc[RT][4];
        #pragma unroll
        for (int jj = 0; jj < 4; jj++) {
            float bv = d2b[a * H_ + tx + 32 * jj];
            #pragma unroll
            for (int i = 0; i < RT; i++) acc[i][jj] = bv;
        }
        const float* W = g_d2T + (size_t)a * H_ * H_;
        for (int k = 0; k < H_; k += 4) {
            float4 dv[RT];
            #pragma unroll
            for (int i = 0; i < RT; i++)
                dv[i] = *reinterpret_cast<const float4*>(&d_s[(ty + 16 * i) * DS + k]);
            #pragma unroll
            for (int kk = 0; kk < 4; kk++) {
                const float* Wr = W + (size_t)(k + kk) * H_;
                #pragma unroll
                for (int jj = 0; jj < 4; jj++) {
                    float wv = Wr[tx + 32 * jj];
                    #pragma unroll
                    for (int i = 0; i < RT; i++)
                        acc[i][jj] += reinterpret_cast<const float*>(&dv[i])[kk] * wv;
                }
            }
        }
        #pragma unroll
        for (int i = 0; i < RT; i++)
            #pragma unroll
            for (int jj = 0; jj < 4; jj++)
                e_s[(ty + 16 * i) * DS + tx + 32 * jj] = fmaxf(acc[i][jj], 0.f);
    }
    __syncthreads();

    // ---- mean / std heads ----
    for (int task = tid; task < nrows * 4; task += NTHREADS) {
        int r = task >> 2, o = task & 3;
        const float* W = (o < 2) ? (mw + ((size_t)a * 2 + o) * H_)
                                 : (sw + ((size_t)a * 2 + (o - 2)) * H_);
        float acc = (o < 2) ? mb[a * 2 + o] : sb[a * 2 + o - 2];
        for (int k = 0; k < H_; k++) acc += e_s[r * DS + k] * W[k];
        if (o >= 2)
            acc = fmaxf(acc, 0.f) + log1pf(expf(-fabsf(acc)));
        ms_s[r * 4 + o] = acc;
    }
    __syncthreads();

    // ---- per-row NLL + ev ----
    {
        double lsum = 0.0, esum = 0.0;
        if (tid < nrows) {
            int b = row0 + tid;
            size_t xb = (((size_t)(t + 1) * A_ + a) * B_ + b) * Y_ + 4 * a;
            float x0 = states[xb + 2], x1 = states[xb + 3];
            float m0 = ms_s[tid * 4 + 0], m1 = ms_s[tid * 4 + 1];
            float s0 = ms_s[tid * 4 + 2], s1 = ms_s[tid * 4 + 3];
            float z0 = (x0 - m0) / s0, z1 = (x1 - m1) / s1;
            const double L2PI = 1.8378770664093453;
            lsum = 0.5 * ((double)(z0 * z0) + (double)(z1 * z1)
                 + 2.0 * ((double)logf(s0) + (double)logf(s1)) + 2.0 * L2PI);
            float dm0 = m0 - x0, dm1 = m1 - x1;
            esum = sqrt((double)dm0 * dm0 + (double)dm1 * dm1);
        }
        #pragma unroll
        for (int o = 16; o; o >>= 1) {
            lsum += __shfl_down_sync(0xffffffffu, lsum, o);
            esum += __shfl_down_sync(0xffffffffu, esum, o);
        }
        if ((tid & 31) == 0) {
            atomicAdd(&g_acc[0], lsum);
            atomicAdd(&g_acc[2], esum);
        }
    }

    // ---- GRU: transposed weights, coalesced scalar loads ----
    const float* WiT = g_WiT + (size_t)a * INP_ * G_;
    const float* WhT = g_WhT + (size_t)a * R_ * G_;
    for (int jc = 0; jc < 4; jc++) {
        const int j0 = jc * 64 + tx;   // gate cols j0, j0+32
        float air[RT][2], aiz[RT][2], ain[RT][2];
        float ahr[RT][2], ahz[RT][2], ahn[RT][2];
        #pragma unroll
        for (int jj = 0; jj < 2; jj++) {
            int j = j0 + 32 * jj;
            float bir = b_ih[a * G_ + j];
            float biz = b_ih[a * G_ + 256 + j];
            float bin = b_ih[a * G_ + 512 + j];
            float bhr = b_hh[a * G_ + j];
            float bhz = b_hh[a * G_ + 256 + j];
            float bhn = b_hh[a * G_ + 512 + j];
            #pragma unroll
            for (int i = 0; i < RT; i++) {
                air[i][jj] = bir; aiz[i][jj] = biz; ain[i][jj] = bin;
                ahr[i][jj] = bhr; ahz[i][jj] = bhz; ahn[i][jj] = bhn;
            }
        }

        // y region (padded k 0..95): gi only
        for (int k = 0; k < 96; k += 4) {
            float4 hv[RT];
            #pragma unroll
            for (int i = 0; i < RT; i++)
                hv[i] = *reinterpret_cast<const float4*>(&enc_s[(ty + 16 * i) * ES + k]);
            #pragma unroll
            for (int kk = 0; kk < 4; kk++) {
                const float* Wr = WiT + (size_t)(k + kk) * G_;
                #pragma unroll
                for (int jj = 0; jj < 2; jj++) {
                    int j = j0 + 32 * jj;
                    float wr = Wr[j];
                    float wz = Wr[256 + j];
                    float wn = Wr[512 + j];
                    #pragma unroll
                    for (int i = 0; i < RT; i++) {
                        float h = reinterpret_cast<const float*>(&hv[i])[kk];
                        air[i][jj] += h * wr;
                        aiz[i][jj] += h * wz;
                        ain[i][jj] += h * wn;
                    }
                }
            }
        }
        // h region (k 0..255): gi (offset 96) and gh together
        for (int k = 0; k < R_; k += 4) {
            float4 hv[RT];
            #pragma unroll
            for (int i = 0; i < RT; i++)
                hv[i] = *reinterpret_cast<const float4*>(&enc_s[(ty + 16 * i) * ES + 96 + k]);
            #pragma unroll
            for (int kk = 0; kk < 4; kk++) {
                const float* Wir = WiT + (size_t)(96 + k + kk) * G_;
                const float* Whr = WhT + (size_t)(k + kk) * G_;
                #pragma unroll
                for (int jj = 0; jj < 2; jj++) {
                    int j = j0 + 32 * jj;
                    float wir = Wir[j];
                    float wiz = Wir[256 + j];
                    float win = Wir[512 + j];
                    float whr = Whr[j];
                    float whz = Whr[256 + j];
                    float whn = Whr[512 + j];
                    #pragma unroll
                    for (int i = 0; i < RT; i++) {
                        float h = reinterpret_cast<const float*>(&hv[i])[kk];
                        air[i][jj] += h * wir;
                        aiz[i][jj] += h * wiz;
                        ain[i][jj] += h * win;
                        ahr[i][jj] += h * whr;
                        ahz[i][jj] += h * whz;
                        ahn[i][jj] += h * whn;
                    }
                }
            }
        }
        // combine + in-place h update
        #pragma unroll
        for (int i = 0; i < RT; i++) {
            int r = ty + 16 * i;
            if (r < nrows) {
                #pragma unroll
                for (int jj = 0; jj < 2; jj++) {
                    int j = j0 + 32 * jj;
                    float rg = 1.f / (1.f + expf(-(air[i][jj] + ahr[i][jj])));
                    float zg = 1.f / (1.f + expf(-(aiz[i][jj] + ahz[i][jj])));
                    float ng = tanhf(ain[i][jj] + rg * ahn[i][jj]);
                    float hold = enc_s[r * ES + 96 + j];
                    float hnew = (1.f - zg) * ng + zg * hold;
                    g_h[((size_t)a * B_ + row0 + r) * R_ + j] = hnew;
                }
            }
        }
    }
}

__global__ void final_kernel(float* out) {
    if (threadIdx.x == 0) {
        const double denom = (double)T_ * A_;
        out[0] = (float)(g_acc[0] / denom);
        out[1] = (float)(g_acc[1] / denom);
        out[2] = (float)(g_acc[2] / denom);
    }
}

extern "C" void kernel_launch(void* const* d_in, const int* in_sizes, int n_in,
                              void* d_out, int out_size) {
    const float* states = (const float*)d_in[0];
    const float* W_ih   = (const float*)d_in[1];
    const float* W_hh   = (const float*)d_in[2];
    const float* b_ih   = (const float*)d_in[3];
    const float* b_hh   = (const float*)d_in[4];
    const float* d1w    = (const float*)d_in[5];
    const float* d1b    = (const float*)d_in[6];
    const float* d2w    = (const float*)d_in[7];
    const float* d2b    = (const float*)d_in[8];
    const float* mw     = (const float*)d_in[9];
    const float* mb     = (const float*)d_in[10];
    const float* sw     = (const float*)d_in[11];
    const float* sb     = (const float*)d_in[12];
    float* out = (float*)d_out;

    const size_t SMEM = (size_t)ROWPAD * (ES + DS + DS + 4) * sizeof(float); // 199,680 B
    cudaFuncSetAttribute(step_kernel, cudaFuncAttributeMaxDynamicSharedMemorySize, (int)SMEM);

    init_kernel<<<256, 256>>>();
    pack_wi_kernel<<<512, 256>>>(W_ih);
    pack_wh_kernel<<<512, 256>>>(W_hh);
    pack_d_kernel<<<256, 256>>>(d1w, d2w);
    ep_kernel<<<(T_ * A_ * B_ + 255) / 256, 256>>>(states);

    dim3 grid(NTILES, A_);
    for (int t = 0; t < T_; t++) {
        step_kernel<<<grid, NTHREADS, SMEM>>>(states, b_ih, b_hh,
                                              d1b, d2b, mw, mb, sw, sb, t);
    }
    final_kernel<<<1, 32>>>(out);
}

// round 5
// speedup vs baseline: 4.9382x; 1.4382x over previous
#include <cuda_runtime.h>
#include <math.h>

#define A_ 10
#define B_ 1024
#define Y_ 94
#define R_ 256
#define H_ 128
#define G_ 768
#define T_ 50
#define IN_ 350
#define INP_ 352     // padded [y(94)+2 zeros | h(256)]
#define FS_ 0.1f

#define BTILE 74
#define NTILES 14      // 14*74 = 1036 >= 1024
#define ROWPAD 80      // 16 warps * RT 5
#define RT 5
#define NTHREADS 512
#define ES 356         // enc row stride (float4-aligned)
#define DS 132         // d/e row stride (float4-aligned)

typedef unsigned long long ull;

__device__ __forceinline__ ull pack2(float x, float y) {
    ull r; asm("mov.b64 %0, {%1, %2};" : "=l"(r) : "f"(x), "f"(y)); return r;
}
__device__ __forceinline__ ull dup2(float x) {
    ull r; asm("mov.b64 %0, {%1, %1};" : "=l"(r) : "f"(x)); return r;
}
__device__ __forceinline__ ull fma2(ull a, ull b, ull c) {
    ull d; asm("fma.rn.f32x2 %0, %1, %2, %3;" : "=l"(d) : "l"(a), "l"(b), "l"(c)); return d;
}
__device__ __forceinline__ float2 unpk2(ull v) {
    float2 f; asm("mov.b64 {%0, %1}, %2;" : "=f"(f.x), "=f"(f.y) : "l"(v)); return f;
}

// scratch (no cudaMalloc allowed) — 16B aligned for 64/128-bit access
__device__ __align__(16) float  g_h[A_ * B_ * R_];
__device__ __align__(16) float  g_WiT[A_ * INP_ * G_];   // [a][k][j]
__device__ __align__(16) float  g_WhT[A_ * R_ * G_];     // [a][k][j]
__device__ __align__(16) float  g_d1T[A_ * R_ * H_];     // [a][k][j]
__device__ __align__(16) float  g_d2T[A_ * H_ * H_];     // [a][k][j]
__device__ double g_acc[3];

__global__ void init_kernel() {
    const size_t n = (size_t)A_ * B_ * R_;
    for (size_t i = (size_t)blockIdx.x * blockDim.x + threadIdx.x; i < n;
         i += (size_t)gridDim.x * blockDim.x)
        g_h[i] = 0.f;
    if (blockIdx.x == 0 && threadIdx.x < 3) g_acc[threadIdx.x] = 0.0;
}

__global__ void pack_wi_kernel(const float* __restrict__ W_ih) {
    const int n = A_ * INP_ * G_;
    for (int i = blockIdx.x * blockDim.x + threadIdx.x; i < n;
         i += gridDim.x * blockDim.x) {
        int j = i % G_;
        int r = i / G_;
        int k = r % INP_;
        int a = r / INP_;
        float v = 0.f;
        if (k < Y_)       v = W_ih[((size_t)a * G_ + j) * IN_ + k];
        else if (k >= 96) v = W_ih[((size_t)a * G_ + j) * IN_ + (k - 2)];
        g_WiT[i] = v;
    }
}
__global__ void pack_wh_kernel(const float* __restrict__ W_hh) {
    const int n = A_ * R_ * G_;
    for (int i = blockIdx.x * blockDim.x + threadIdx.x; i < n;
         i += gridDim.x * blockDim.x) {
        int j = i % G_;
        int r = i / G_;
        int k = r % R_;
        int a = r / R_;
        g_WhT[i] = W_hh[((size_t)a * G_ + j) * R_ + k];
    }
}
__global__ void pack_d_kernel(const float* __restrict__ d1w,
                              const float* __restrict__ d2w) {
    const int n1 = A_ * R_ * H_;
    for (int i = blockIdx.x * blockDim.x + threadIdx.x; i < n1;
         i += gridDim.x * blockDim.x) {
        int j = i % H_;
        int r = i / H_;
        int k = r % R_;
        int a = r / R_;
        g_d1T[i] = d1w[((size_t)a * H_ + j) * R_ + k];
    }
    const int n2 = A_ * H_ * H_;
    for (int i = blockIdx.x * blockDim.x + threadIdx.x; i < n2;
         i += gridDim.x * blockDim.x) {
        int j = i % H_;
        int r = i / H_;
        int k = r % H_;
        int a = r / H_;
        g_d2T[i] = d2w[((size_t)a * H_ + j) * H_ + k];
    }
}

__global__ void ep_kernel(const float* __restrict__ states) {
    int idx = blockIdx.x * blockDim.x + threadIdx.x;
    double e = 0.0;
    if (idx < T_ * A_ * B_) {
        int t = idx / (A_ * B_);
        int r = idx - t * (A_ * B_);
        int a = r >> 10;
        int b = r & 1023;
        size_t base = (((size_t)t * A_ + a) * B_ + b) * Y_ + 4 * a;
        float f0 = states[base + 0], f1 = states[base + 1];
        float f2 = states[base + 2], f3 = states[base + 3];
        size_t base1 = base + (size_t)A_ * B_ * Y_;
        float g0 = states[base1 + 0], g1 = states[base1 + 1];
        float d0 = f0 + f2 * FS_ - g0;
        float d1 = f1 + f3 * FS_ - g1;
        e = sqrt((double)d0 * d0 + (double)d1 * d1);
    }
    #pragma unroll
    for (int o = 16; o; o >>= 1) e += __shfl_down_sync(0xffffffffu, e, o);
    if ((threadIdx.x & 31) == 0) atomicAdd(&g_acc[1], e);
}

__global__ __launch_bounds__(NTHREADS) void step_kernel(
    const float* __restrict__ states,
    const float* __restrict__ b_ih, const float* __restrict__ b_hh,
    const float* __restrict__ d1b,  const float* __restrict__ d2b,
    const float* __restrict__ mw,   const float* __restrict__ mb,
    const float* __restrict__ sw,   const float* __restrict__ sb,
    int t)
{
    extern __shared__ float sm[];
    float* enc_s = sm;                         // ROWPAD*ES  [y(96 padded)|h(256)]
    float* d_s   = enc_s + ROWPAD * ES;        // ROWPAD*DS
    float* e_s   = d_s   + ROWPAD * DS;        // ROWPAD*DS
    float* ms_s  = e_s   + ROWPAD * DS;        // ROWPAD*4

    const int a     = blockIdx.y;
    const int row0  = blockIdx.x * BTILE;
    const int nrows = min(BTILE, B_ - row0);
    const int tid   = threadIdx.x;
    const int tx    = tid & 31;
    const int ty    = tid >> 5;
    const int cp    = 2 * tx;       // column-pair base within 64-col group

    // ---- stage enc = [y | 0 0 | h] ----
    const float* hg = g_h + ((size_t)a * B_ + row0) * R_;
    for (int i = tid; i < ROWPAD * R_; i += NTHREADS) {
        int r = i >> 8, k = i & 255;
        enc_s[r * ES + 96 + k] = (r < nrows) ? hg[(size_t)r * R_ + k] : 0.f;
    }
    const float* yg = states + (((size_t)t * A_ + a) * B_ + row0) * Y_;
    for (int i = tid; i < ROWPAD * 96; i += NTHREADS) {
        int r = i / 96, k = i - r * 96;
        enc_s[r * ES + k] = (r < nrows && k < Y_) ? yg[(size_t)r * Y_ + k] : 0.f;
    }
    __syncthreads();

    // ---- D1: col-pairs (cp, cp+1) and (cp+64, cp+65) ----
    {
        ull acc[RT][2];
        {
            ull b0 = *reinterpret_cast<const ull*>(&d1b[a * H_ + cp]);
            ull b1 = *reinterpret_cast<const ull*>(&d1b[a * H_ + cp + 64]);
            #pragma unroll
            for (int i = 0; i < RT; i++) { acc[i][0] = b0; acc[i][1] = b1; }
        }
        const float* W = g_d1T + (size_t)a * R_ * H_;
        for (int k = 0; k < R_; k += 4) {
            float4 hv[RT];
            #pragma unroll
            for (int i = 0; i < RT; i++)
                hv[i] = *reinterpret_cast<const float4*>(&enc_s[(ty + 16 * i) * ES + 96 + k]);
            #pragma unroll
            for (int kk = 0; kk < 4; kk++) {
                const float* Wr = W + (size_t)(k + kk) * H_;
                ull w0 = *reinterpret_cast<const ull*>(&Wr[cp]);
                ull w1 = *reinterpret_cast<const ull*>(&Wr[cp + 64]);
                #pragma unroll
                for (int i = 0; i < RT; i++) {
                    ull hh = dup2(reinterpret_cast<const float*>(&hv[i])[kk]);
                    acc[i][0] = fma2(hh, w0, acc[i][0]);
                    acc[i][1] = fma2(hh, w1, acc[i][1]);
                }
            }
        }
        #pragma unroll
        for (int i = 0; i < RT; i++) {
            int r = ty + 16 * i;
            #pragma unroll
            for (int jj = 0; jj < 2; jj++) {
                float2 v = unpk2(acc[i][jj]);
                v.x = fmaxf(v.x, 0.f); v.y = fmaxf(v.y, 0.f);
                *reinterpret_cast<ull*>(&d_s[r * DS + cp + 64 * jj]) = pack2(v.x, v.y);
            }
        }
    }
    __syncthreads();

    // ---- D2 ----
    {
        ull acc[RT][2];
        {
            ull b0 = *reinterpret_cast<const ull*>(&d2b[a * H_ + cp]);
            ull b1 = *reinterpret_cast<const ull*>(&d2b[a * H_ + cp + 64]);
            #pragma unroll
            for (int i = 0; i < RT; i++) { acc[i][0] = b0; acc[i][1] = b1; }
        }
        const float* W = g_d2T + (size_t)a * H_ * H_;
        for (int k = 0; k < H_; k += 4) {
            float4 dv[RT];
            #pragma unroll
            for (int i = 0; i < RT; i++)
                dv[i] = *reinterpret_cast<const float4*>(&d_s[(ty + 16 * i) * DS + k]);
            #pragma unroll
            for (int kk = 0; kk < 4; kk++) {
                const float* Wr = W + (size_t)(k + kk) * H_;
                ull w0 = *reinterpret_cast<const ull*>(&Wr[cp]);
                ull w1 = *reinterpret_cast<const ull*>(&Wr[cp + 64]);
                #pragma unroll
                for (int i = 0; i < RT; i++) {
                    ull hh = dup2(reinterpret_cast<const float*>(&dv[i])[kk]);
                    acc[i][0] = fma2(hh, w0, acc[i][0]);
                    acc[i][1] = fma2(hh, w1, acc[i][1]);
                }
            }
        }
        #pragma unroll
        for (int i = 0; i < RT; i++) {
            int r = ty + 16 * i;
            #pragma unroll
            for (int jj = 0; jj < 2; jj++) {
                float2 v = unpk2(acc[i][jj]);
                v.x = fmaxf(v.x, 0.f); v.y = fmaxf(v.y, 0.f);
                *reinterpret_cast<ull*>(&e_s[r * DS + cp + 64 * jj]) = pack2(v.x, v.y);
            }
        }
    }
    __syncthreads();

    // ---- mean / std heads ----
    for (int task = tid; task < nrows * 4; task += NTHREADS) {
        int r = task >> 2, o = task & 3;
        const float* W = (o < 2) ? (mw + ((size_t)a * 2 + o) * H_)
                                 : (sw + ((size_t)a * 2 + (o - 2)) * H_);
        float acc = (o < 2) ? mb[a * 2 + o] : sb[a * 2 + o - 2];
        for (int k = 0; k < H_; k++) acc += e_s[r * DS + k] * W[k];
        if (o >= 2)
            acc = fmaxf(acc, 0.f) + log1pf(expf(-fabsf(acc)));
        ms_s[r * 4 + o] = acc;
    }
    __syncthreads();

    // ---- per-row NLL + ev ----
    {
        double lsum = 0.0, esum = 0.0;
        if (tid < nrows) {
            int b = row0 + tid;
            size_t xb = (((size_t)(t + 1) * A_ + a) * B_ + b) * Y_ + 4 * a;
            float x0 = states[xb + 2], x1 = states[xb + 3];
            float m0 = ms_s[tid * 4 + 0], m1 = ms_s[tid * 4 + 1];
            float s0 = ms_s[tid * 4 + 2], s1 = ms_s[tid * 4 + 3];
            float z0 = (x0 - m0) / s0, z1 = (x1 - m1) / s1;
            const double L2PI = 1.8378770664093453;
            lsum = 0.5 * ((double)(z0 * z0) + (double)(z1 * z1)
                 + 2.0 * ((double)logf(s0) + (double)logf(s1)) + 2.0 * L2PI);
            float dm0 = m0 - x0, dm1 = m1 - x1;
            esum = sqrt((double)dm0 * dm0 + (double)dm1 * dm1);
        }
        #pragma unroll
        for (int o = 16; o; o >>= 1) {
            lsum += __shfl_down_sync(0xffffffffu, lsum, o);
            esum += __shfl_down_sync(0xffffffffu, esum, o);
        }
        if ((tid & 31) == 0) {
            atomicAdd(&g_acc[0], lsum);
            atomicAdd(&g_acc[2], esum);
        }
    }

    // ---- GRU: col-pair packed f32x2 ----
    const float* WiT = g_WiT + (size_t)a * INP_ * G_;
    const float* WhT = g_WhT + (size_t)a * R_ * G_;
    for (int jc = 0; jc < 4; jc++) {
        const int j0 = jc * 64 + cp;   // even col-pair base
        ull air[RT], aiz[RT], ain[RT], ahr[RT], ahz[RT], ahn[RT];
        {
            ull bir = *reinterpret_cast<const ull*>(&b_ih[a * G_ + j0]);
            ull biz = *reinterpret_cast<const ull*>(&b_ih[a * G_ + 256 + j0]);
            ull bin = *reinterpret_cast<const ull*>(&b_ih[a * G_ + 512 + j0]);
            ull bhr = *reinterpret_cast<const ull*>(&b_hh[a * G_ + j0]);
            ull bhz = *reinterpret_cast<const ull*>(&b_hh[a * G_ + 256 + j0]);
            ull bhn = *reinterpret_cast<const ull*>(&b_hh[a * G_ + 512 + j0]);
            #pragma unroll
            for (int i = 0; i < RT; i++) {
                air[i] = bir; aiz[i] = biz; ain[i] = bin;
                ahr[i] = bhr; ahz[i] = bhz; ahn[i] = bhn;
            }
        }

        // y region (padded k 0..95): gi only
        for (int k = 0; k < 96; k += 4) {
            float4 hv[RT];
            #pragma unroll
            for (int i = 0; i < RT; i++)
                hv[i] = *reinterpret_cast<const float4*>(&enc_s[(ty + 16 * i) * ES + k]);
            #pragma unroll
            for (int kk = 0; kk < 4; kk++) {
                const float* Wr = WiT + (size_t)(k + kk) * G_;
                ull wr = *reinterpret_cast<const ull*>(&Wr[j0]);
                ull wz = *reinterpret_cast<const ull*>(&Wr[256 + j0]);
                ull wn = *reinterpret_cast<const ull*>(&Wr[512 + j0]);
                #pragma unroll
                for (int i = 0; i < RT; i++) {
                    ull hh = dup2(reinterpret_cast<const float*>(&hv[i])[kk]);
                    air[i] = fma2(hh, wr, air[i]);
                    aiz[i] = fma2(hh, wz, aiz[i]);
                    ain[i] = fma2(hh, wn, ain[i]);
                }
            }
        }
        // h region (k 0..255): gi (offset 96) and gh together
        for (int k = 0; k < R_; k += 4) {
            float4 hv[RT];
            #pragma unroll
            for (int i = 0; i < RT; i++)
                hv[i] = *reinterpret_cast<const float4*>(&enc_s[(ty + 16 * i) * ES + 96 + k]);
            #pragma unroll
            for (int kk = 0; kk < 4; kk++) {
                const float* Wir = WiT + (size_t)(96 + k + kk) * G_;
                const float* Whr = WhT + (size_t)(k + kk) * G_;
                ull wir = *reinterpret_cast<const ull*>(&Wir[j0]);
                ull wiz = *reinterpret_cast<const ull*>(&Wir[256 + j0]);
                ull win = *reinterpret_cast<const ull*>(&Wir[512 + j0]);
                ull whr = *reinterpret_cast<const ull*>(&Whr[j0]);
                ull whz = *reinterpret_cast<const ull*>(&Whr[256 + j0]);
                ull whn = *reinterpret_cast<const ull*>(&Whr[512 + j0]);
                #pragma unroll
                for (int i = 0; i < RT; i++) {
                    ull hh = dup2(reinterpret_cast<const float*>(&hv[i])[kk]);
                    air[i] = fma2(hh, wir, air[i]);
                    aiz[i] = fma2(hh, wiz, aiz[i]);
                    ain[i] = fma2(hh, win, ain[i]);
                    ahr[i] = fma2(hh, whr, ahr[i]);
                    ahz[i] = fma2(hh, whz, ahz[i]);
                    ahn[i] = fma2(hh, whn, ahn[i]);
                }
            }
        }
        // combine + in-place h update (64-bit store of col pair)
        #pragma unroll
        for (int i = 0; i < RT; i++) {
            int r = ty + 16 * i;
            if (r < nrows) {
                float2 vir = unpk2(air[i]), viz = unpk2(aiz[i]), vin = unpk2(ain[i]);
                float2 vhr = unpk2(ahr[i]), vhz = unpk2(ahz[i]), vhn = unpk2(ahn[i]);
                float2 hold = *reinterpret_cast<const float2*>(&enc_s[r * ES + 96 + j0]);
                float rg0 = 1.f / (1.f + expf(-(vir.x + vhr.x)));
                float rg1 = 1.f / (1.f + expf(-(vir.y + vhr.y)));
                float zg0 = 1.f / (1.f + expf(-(viz.x + vhz.x)));
                float zg1 = 1.f / (1.f + expf(-(viz.y + vhz.y)));
                float ng0 = tanhf(vin.x + rg0 * vhn.x);
                float ng1 = tanhf(vin.y + rg1 * vhn.y);
                float h0 = (1.f - zg0) * ng0 + zg0 * hold.x;
                float h1 = (1.f - zg1) * ng1 + zg1 * hold.y;
                *reinterpret_cast<ull*>(&g_h[((size_t)a * B_ + row0 + r) * R_ + j0]) = pack2(h0, h1);
            }
        }
    }
}

__global__ void final_kernel(float* out) {
    if (threadIdx.x == 0) {
        const double denom = (double)T_ * A_;
        out[0] = (float)(g_acc[0] / denom);
        out[1] = (float)(g_acc[1] / denom);
        out[2] = (float)(g_acc[2] / denom);
    }
}

extern "C" void kernel_launch(void* const* d_in, const int* in_sizes, int n_in,
                              void* d_out, int out_size) {
    const float* states = (const float*)d_in[0];
    const float* W_ih   = (const float*)d_in[1];
    const float* W_hh   = (const float*)d_in[2];
    const float* b_ih   = (const float*)d_in[3];
    const float* b_hh   = (const float*)d_in[4];
    const float* d1w    = (const float*)d_in[5];
    const float* d1b    = (const float*)d_in[6];
    const float* d2w    = (const float*)d_in[7];
    const float* d2b    = (const float*)d_in[8];
    const float* mw     = (const float*)d_in[9];
    const float* mb     = (const float*)d_in[10];
    const float* sw     = (const float*)d_in[11];
    const float* sb     = (const float*)d_in[12];
    float* out = (float*)d_out;

    const size_t SMEM = (size_t)ROWPAD * (ES + DS + DS + 4) * sizeof(float); // 199,680 B
    cudaFuncSetAttribute(step_kernel, cudaFuncAttributeMaxDynamicSharedMemorySize, (int)SMEM);

    init_kernel<<<256, 256>>>();
    pack_wi_kernel<<<512, 256>>>(W_ih);
    pack_wh_kernel<<<512, 256>>>(W_hh);
    pack_d_kernel<<<256, 256>>>(d1w, d2w);
    ep_kernel<<<(T_ * A_ * B_ + 255) / 256, 256>>>(states);

    dim3 grid(NTILES, A_);
    for (int t = 0; t < T_; t++) {
        step_kernel<<<grid, NTHREADS, SMEM>>>(states, b_ih, b_hh,
                                              d1b, d2b, mw, mb, sw, sb, t);
    }
    final_kernel<<<1, 32>>>(out);
}

// round 6
// speedup vs baseline: 5.2480x; 1.0627x over previous
#include <cuda_runtime.h>
#include <math.h>

#define A_ 10
#define B_ 1024
#define Y_ 94
#define R_ 256
#define H_ 128
#define G_ 768
#define T_ 50
#define IN_ 350
#define INP_ 352     // padded [y(94)+2 zeros | h(256)]
#define FS_ 0.1f

#define BTILE 37
#define NTILES 28      // 28*37 = 1036 >= 1024
#define ROWPAD 40      // 8 warps * RT 5
#define RT 5
#define NTHREADS 256
#define ES 356         // enc row stride (float4-aligned)
#define DS 132         // d/e row stride (float4-aligned)

typedef unsigned long long ull;

__device__ __forceinline__ ull pack2(float x, float y) {
    ull r; asm("mov.b64 %0, {%1, %2};" : "=l"(r) : "f"(x), "f"(y)); return r;
}
__device__ __forceinline__ ull dup2(float x) {
    ull r; asm("mov.b64 %0, {%1, %1};" : "=l"(r) : "f"(x)); return r;
}
__device__ __forceinline__ ull fma2(ull a, ull b, ull c) {
    ull d; asm("fma.rn.f32x2 %0, %1, %2, %3;" : "=l"(d) : "l"(a), "l"(b), "l"(c)); return d;
}
__device__ __forceinline__ float2 unpk2(ull v) {
    float2 f; asm("mov.b64 {%0, %1}, %2;" : "=f"(f.x), "=f"(f.y) : "l"(v)); return f;
}

// scratch (no cudaMalloc allowed) — 16B aligned for 64/128-bit access
__device__ __align__(16) float  g_h[A_ * B_ * R_];
__device__ __align__(16) float  g_WiT[A_ * INP_ * G_];   // [a][k][j]
__device__ __align__(16) float  g_WhT[A_ * R_ * G_];     // [a][k][j]
__device__ __align__(16) float  g_d1T[A_ * R_ * H_];     // [a][k][j]
__device__ __align__(16) float  g_d2T[A_ * H_ * H_];     // [a][k][j]
__device__ double g_acc[3];

__global__ void init_kernel() {
    const size_t n = (size_t)A_ * B_ * R_;
    for (size_t i = (size_t)blockIdx.x * blockDim.x + threadIdx.x; i < n;
         i += (size_t)gridDim.x * blockDim.x)
        g_h[i] = 0.f;
    if (blockIdx.x == 0 && threadIdx.x < 3) g_acc[threadIdx.x] = 0.0;
}

__global__ void pack_wi_kernel(const float* __restrict__ W_ih) {
    const int n = A_ * INP_ * G_;
    for (int i = blockIdx.x * blockDim.x + threadIdx.x; i < n;
         i += gridDim.x * blockDim.x) {
        int j = i % G_;
        int r = i / G_;
        int k = r % INP_;
        int a = r / INP_;
        float v = 0.f;
        if (k < Y_)       v = W_ih[((size_t)a * G_ + j) * IN_ + k];
        else if (k >= 96) v = W_ih[((size_t)a * G_ + j) * IN_ + (k - 2)];
        g_WiT[i] = v;
    }
}
__global__ void pack_wh_kernel(const float* __restrict__ W_hh) {
    const int n = A_ * R_ * G_;
    for (int i = blockIdx.x * blockDim.x + threadIdx.x; i < n;
         i += gridDim.x * blockDim.x) {
        int j = i % G_;
        int r = i / G_;
        int k = r % R_;
        int a = r / R_;
        g_WhT[i] = W_hh[((size_t)a * G_ + j) * R_ + k];
    }
}
__global__ void pack_d_kernel(const float* __restrict__ d1w,
                              const float* __restrict__ d2w) {
    const int n1 = A_ * R_ * H_;
    for (int i = blockIdx.x * blockDim.x + threadIdx.x; i < n1;
         i += gridDim.x * blockDim.x) {
        int j = i % H_;
        int r = i / H_;
        int k = r % R_;
        int a = r / R_;
        g_d1T[i] = d1w[((size_t)a * H_ + j) * R_ + k];
    }
    const int n2 = A_ * H_ * H_;
    for (int i = blockIdx.x * blockDim.x + threadIdx.x; i < n2;
         i += gridDim.x * blockDim.x) {
        int j = i % H_;
        int r = i / H_;
        int k = r % H_;
        int a = r / H_;
        g_d2T[i] = d2w[((size_t)a * H_ + j) * H_ + k];
    }
}

__global__ void ep_kernel(const float* __restrict__ states) {
    int idx = blockIdx.x * blockDim.x + threadIdx.x;
    double e = 0.0;
    if (idx < T_ * A_ * B_) {
        int t = idx / (A_ * B_);
        int r = idx - t * (A_ * B_);
        int a = r >> 10;
        int b = r & 1023;
        size_t base = (((size_t)t * A_ + a) * B_ + b) * Y_ + 4 * a;
        float f0 = states[base + 0], f1 = states[base + 1];
        float f2 = states[base + 2], f3 = states[base + 3];
        size_t base1 = base + (size_t)A_ * B_ * Y_;
        float g0 = states[base1 + 0], g1 = states[base1 + 1];
        float d0 = f0 + f2 * FS_ - g0;
        float d1 = f1 + f3 * FS_ - g1;
        e = sqrt((double)d0 * d0 + (double)d1 * d1);
    }
    #pragma unroll
    for (int o = 16; o; o >>= 1) e += __shfl_down_sync(0xffffffffu, e, o);
    if ((threadIdx.x & 31) == 0) atomicAdd(&g_acc[1], e);
}

__global__ __launch_bounds__(NTHREADS, 2) void step_kernel(
    const float* __restrict__ states,
    const float* __restrict__ b_ih, const float* __restrict__ b_hh,
    const float* __restrict__ d1b,  const float* __restrict__ d2b,
    const float* __restrict__ mw,   const float* __restrict__ mb,
    const float* __restrict__ sw,   const float* __restrict__ sb,
    int t)
{
    extern __shared__ float sm[];
    float* enc_s = sm;                         // ROWPAD*ES  [y(96 padded)|h(256)]
    float* d_s   = enc_s + ROWPAD * ES;        // ROWPAD*DS
    float* e_s   = d_s   + ROWPAD * DS;        // ROWPAD*DS
    float* ms_s  = e_s   + ROWPAD * DS;        // ROWPAD*4

    const int a     = blockIdx.y;
    const int row0  = blockIdx.x * BTILE;
    const int nrows = min(BTILE, B_ - row0);
    const int tid   = threadIdx.x;
    const int tx    = tid & 31;
    const int ty    = tid >> 5;     // warp 0..7
    const int cp    = 2 * tx;       // column-pair base within 64-col group

    // ---- stage enc = [y | 0 0 | h] ----
    const float* hg = g_h + ((size_t)a * B_ + row0) * R_;
    for (int i = tid; i < ROWPAD * R_; i += NTHREADS) {
        int r = i >> 8, k = i & 255;
        enc_s[r * ES + 96 + k] = (r < nrows) ? hg[(size_t)r * R_ + k] : 0.f;
    }
    const float* yg = states + (((size_t)t * A_ + a) * B_ + row0) * Y_;
    for (int i = tid; i < ROWPAD * 96; i += NTHREADS) {
        int r = i / 96, k = i - r * 96;
        enc_s[r * ES + k] = (r < nrows && k < Y_) ? yg[(size_t)r * Y_ + k] : 0.f;
    }
    __syncthreads();

    // ---- D1: col-pairs (cp, cp+1) and (cp+64, cp+65), rows ty+8i ----
    {
        ull acc[RT][2];
        {
            ull b0 = *reinterpret_cast<const ull*>(&d1b[a * H_ + cp]);
            ull b1 = *reinterpret_cast<const ull*>(&d1b[a * H_ + cp + 64]);
            #pragma unroll
            for (int i = 0; i < RT; i++) { acc[i][0] = b0; acc[i][1] = b1; }
        }
        const float* W = g_d1T + (size_t)a * R_ * H_;
        for (int k = 0; k < R_; k += 4) {
            float4 hv[RT];
            #pragma unroll
            for (int i = 0; i < RT; i++)
                hv[i] = *reinterpret_cast<const float4*>(&enc_s[(ty + 8 * i) * ES + 96 + k]);
            #pragma unroll
            for (int kk = 0; kk < 4; kk++) {
                const float* Wr = W + (size_t)(k + kk) * H_;
                ull w0 = *reinterpret_cast<const ull*>(&Wr[cp]);
                ull w1 = *reinterpret_cast<const ull*>(&Wr[cp + 64]);
                #pragma unroll
                for (int i = 0; i < RT; i++) {
                    ull hh = dup2(reinterpret_cast<const float*>(&hv[i])[kk]);
                    acc[i][0] = fma2(hh, w0, acc[i][0]);
                    acc[i][1] = fma2(hh, w1, acc[i][1]);
                }
            }
        }
        #pragma unroll
        for (int i = 0; i < RT; i++) {
            int r = ty + 8 * i;
            #pragma unroll
            for (int jj = 0; jj < 2; jj++) {
                float2 v = unpk2(acc[i][jj]);
                v.x = fmaxf(v.x, 0.f); v.y = fmaxf(v.y, 0.f);
                *reinterpret_cast<ull*>(&d_s[r * DS + cp + 64 * jj]) = pack2(v.x, v.y);
            }
        }
    }
    __syncthreads();

    // ---- D2 ----
    {
        ull acc[RT][2];
        {
            ull b0 = *reinterpret_cast<const ull*>(&d2b[a * H_ + cp]);
            ull b1 = *reinterpret_cast<const ull*>(&d2b[a * H_ + cp + 64]);
            #pragma unroll
            for (int i = 0; i < RT; i++) { acc[i][0] = b0; acc[i][1] = b1; }
        }
        const float* W = g_d2T + (size_t)a * H_ * H_;
        for (int k = 0; k < H_; k += 4) {
            float4 dv[RT];
            #pragma unroll
            for (int i = 0; i < RT; i++)
                dv[i] = *reinterpret_cast<const float4*>(&d_s[(ty + 8 * i) * DS + k]);
            #pragma unroll
            for (int kk = 0; kk < 4; kk++) {
                const float* Wr = W + (size_t)(k + kk) * H_;
                ull w0 = *reinterpret_cast<const ull*>(&Wr[cp]);
                ull w1 = *reinterpret_cast<const ull*>(&Wr[cp + 64]);
                #pragma unroll
                for (int i = 0; i < RT; i++) {
                    ull hh = dup2(reinterpret_cast<const float*>(&dv[i])[kk]);
                    acc[i][0] = fma2(hh, w0, acc[i][0]);
                    acc[i][1] = fma2(hh, w1, acc[i][1]);
                }
            }
        }
        #pragma unroll
        for (int i = 0; i < RT; i++) {
            int r = ty + 8 * i;
            #pragma unroll
            for (int jj = 0; jj < 2; jj++) {
                float2 v = unpk2(acc[i][jj]);
                v.x = fmaxf(v.x, 0.f); v.y = fmaxf(v.y, 0.f);
                *reinterpret_cast<ull*>(&e_s[r * DS + cp + 64 * jj]) = pack2(v.x, v.y);
            }
        }
    }
    __syncthreads();

    // ---- mean / std heads ----
    for (int task = tid; task < nrows * 4; task += NTHREADS) {
        int r = task >> 2, o = task & 3;
        const float* W = (o < 2) ? (mw + ((size_t)a * 2 + o) * H_)
                                 : (sw + ((size_t)a * 2 + (o - 2)) * H_);
        float acc = (o < 2) ? mb[a * 2 + o] : sb[a * 2 + o - 2];
        for (int k = 0; k < H_; k++) acc += e_s[r * DS + k] * W[k];
        if (o >= 2)
            acc = fmaxf(acc, 0.f) + log1pf(expf(-fabsf(acc)));
        ms_s[r * 4 + o] = acc;
    }
    __syncthreads();

    // ---- per-row NLL + ev ----
    {
        double lsum = 0.0, esum = 0.0;
        if (tid < nrows) {
            int b = row0 + tid;
            size_t xb = (((size_t)(t + 1) * A_ + a) * B_ + b) * Y_ + 4 * a;
            float x0 = states[xb + 2], x1 = states[xb + 3];
            float m0 = ms_s[tid * 4 + 0], m1 = ms_s[tid * 4 + 1];
            float s0 = ms_s[tid * 4 + 2], s1 = ms_s[tid * 4 + 3];
            float z0 = (x0 - m0) / s0, z1 = (x1 - m1) / s1;
            const double L2PI = 1.8378770664093453;
            lsum = 0.5 * ((double)(z0 * z0) + (double)(z1 * z1)
                 + 2.0 * ((double)logf(s0) + (double)logf(s1)) + 2.0 * L2PI);
            float dm0 = m0 - x0, dm1 = m1 - x1;
            esum = sqrt((double)dm0 * dm0 + (double)dm1 * dm1);
        }
        #pragma unroll
        for (int o = 16; o; o >>= 1) {
            lsum += __shfl_down_sync(0xffffffffu, lsum, o);
            esum += __shfl_down_sync(0xffffffffu, esum, o);
        }
        if ((tid & 31) == 0) {
            atomicAdd(&g_acc[0], lsum);
            atomicAdd(&g_acc[2], esum);
        }
    }

    // ---- GRU: col-pair packed f32x2 ----
    const float* WiT = g_WiT + (size_t)a * INP_ * G_;
    const float* WhT = g_WhT + (size_t)a * R_ * G_;
    for (int jc = 0; jc < 4; jc++) {
        const int j0 = jc * 64 + cp;   // even col-pair base
        ull air[RT], aiz[RT], ain[RT], ahr[RT], ahz[RT], ahn[RT];
        {
            ull bir = *reinterpret_cast<const ull*>(&b_ih[a * G_ + j0]);
            ull biz = *reinterpret_cast<const ull*>(&b_ih[a * G_ + 256 + j0]);
            ull bin = *reinterpret_cast<const ull*>(&b_ih[a * G_ + 512 + j0]);
            ull bhr = *reinterpret_cast<const ull*>(&b_hh[a * G_ + j0]);
            ull bhz = *reinterpret_cast<const ull*>(&b_hh[a * G_ + 256 + j0]);
            ull bhn = *reinterpret_cast<const ull*>(&b_hh[a * G_ + 512 + j0]);
            #pragma unroll
            for (int i = 0; i < RT; i++) {
                air[i] = bir; aiz[i] = biz; ain[i] = bin;
                ahr[i] = bhr; ahz[i] = bhz; ahn[i] = bhn;
            }
        }

        // y region (padded k 0..95): gi only
        for (int k = 0; k < 96; k += 4) {
            float4 hv[RT];
            #pragma unroll
            for (int i = 0; i < RT; i++)
                hv[i] = *reinterpret_cast<const float4*>(&enc_s[(ty + 8 * i) * ES + k]);
            #pragma unroll
            for (int kk = 0; kk < 4; kk++) {
                const float* Wr = WiT + (size_t)(k + kk) * G_;
                ull wr = *reinterpret_cast<const ull*>(&Wr[j0]);
                ull wz = *reinterpret_cast<const ull*>(&Wr[256 + j0]);
                ull wn = *reinterpret_cast<const ull*>(&Wr[512 + j0]);
                #pragma unroll
                for (int i = 0; i < RT; i++) {
                    ull hh = dup2(reinterpret_cast<const float*>(&hv[i])[kk]);
                    air[i] = fma2(hh, wr, air[i]);
                    aiz[i] = fma2(hh, wz, aiz[i]);
                    ain[i] = fma2(hh, wn, ain[i]);
                }
            }
        }
        // h region (k 0..255): gi (offset 96) and gh together
        for (int k = 0; k < R_; k += 4) {
            float4 hv[RT];
            #pragma unroll
            for (int i = 0; i < RT; i++)
                hv[i] = *reinterpret_cast<const float4*>(&enc_s[(ty + 8 * i) * ES + 96 + k]);
            #pragma unroll
            for (int kk = 0; kk < 4; kk++) {
                const float* Wir = WiT + (size_t)(96 + k + kk) * G_;
                const float* Whr = WhT + (size_t)(k + kk) * G_;
                ull wir = *reinterpret_cast<const ull*>(&Wir[j0]);
                ull wiz = *reinterpret_cast<const ull*>(&Wir[256 + j0]);
                ull win = *reinterpret_cast<const ull*>(&Wir[512 + j0]);
                ull whr = *reinterpret_cast<const ull*>(&Whr[j0]);
                ull whz = *reinterpret_cast<const ull*>(&Whr[256 + j0]);
                ull whn = *reinterpret_cast<const ull*>(&Whr[512 + j0]);
                #pragma unroll
                for (int i = 0; i < RT; i++) {
                    ull hh = dup2(reinterpret_cast<const float*>(&hv[i])[kk]);
                    air[i] = fma2(hh, wir, air[i]);
                    aiz[i] = fma2(hh, wiz, aiz[i]);
                    ain[i] = fma2(hh, win, ain[i]);
                    ahr[i] = fma2(hh, whr, ahr[i]);
                    ahz[i] = fma2(hh, whz, ahz[i]);
                    ahn[i] = fma2(hh, whn, ahn[i]);
                }
            }
        }
        // combine + in-place h update (64-bit store of col pair)
        #pragma unroll
        for (int i = 0; i < RT; i++) {
            int r = ty + 8 * i;
            if (r < nrows) {
                float2 vir = unpk2(air[i]), viz = unpk2(aiz[i]), vin = unpk2(ain[i]);
                float2 vhr = unpk2(ahr[i]), vhz = unpk2(ahz[i]), vhn = unpk2(ahn[i]);
                float2 hold = *reinterpret_cast<const float2*>(&enc_s[r * ES + 96 + j0]);
                float rg0 = 1.f / (1.f + expf(-(vir.x + vhr.x)));
                float rg1 = 1.f / (1.f + expf(-(vir.y + vhr.y)));
                float zg0 = 1.f / (1.f + expf(-(viz.x + vhz.x)));
                float zg1 = 1.f / (1.f + expf(-(viz.y + vhz.y)));
                float ng0 = tanhf(vin.x + rg0 * vhn.x);
                float ng1 = tanhf(vin.y + rg1 * vhn.y);
                float h0 = (1.f - zg0) * ng0 + zg0 * hold.x;
                float h1 = (1.f - zg1) * ng1 + zg1 * hold.y;
                *reinterpret_cast<ull*>(&g_h[((size_t)a * B_ + row0 + r) * R_ + j0]) = pack2(h0, h1);
            }
        }
    }
}

__global__ void final_kernel(float* out) {
    if (threadIdx.x == 0) {
        const double denom = (double)T_ * A_;
        out[0] = (float)(g_acc[0] / denom);
        out[1] = (float)(g_acc[1] / denom);
        out[2] = (float)(g_acc[2] / denom);
    }
}

extern "C" void kernel_launch(void* const* d_in, const int* in_sizes, int n_in,
                              void* d_out, int out_size) {
    const float* states = (const float*)d_in[0];
    const float* W_ih   = (const float*)d_in[1];
    const float* W_hh   = (const float*)d_in[2];
    const float* b_ih   = (const float*)d_in[3];
    const float* b_hh   = (const float*)d_in[4];
    const float* d1w    = (const float*)d_in[5];
    const float* d1b    = (const float*)d_in[6];
    const float* d2w    = (const float*)d_in[7];
    const float* d2b    = (const float*)d_in[8];
    const float* mw     = (const float*)d_in[9];
    const float* mb     = (const float*)d_in[10];
    const float* sw     = (const float*)d_in[11];
    const float* sb     = (const float*)d_in[12];
    float* out = (float*)d_out;

    const size_t SMEM = (size_t)ROWPAD * (ES + DS + DS + 4) * sizeof(float); // 99,840 B
    cudaFuncSetAttribute(step_kernel, cudaFuncAttributeMaxDynamicSharedMemorySize, (int)SMEM);

    init_kernel<<<256, 256>>>();
    pack_wi_kernel<<<512, 256>>>(W_ih);
    pack_wh_kernel<<<512, 256>>>(W_hh);
    pack_d_kernel<<<256, 256>>>(d1w, d2w);
    ep_kernel<<<(T_ * A_ * B_ + 255) / 256, 256>>>(states);

    dim3 grid(NTILES, A_);
    for (int t = 0; t < T_; t++) {
        step_kernel<<<grid, NTHREADS, SMEM>>>(states, b_ih, b_hh,
                                              d1b, d2b, mw, mb, sw, sb, t);
    }
    final_kernel<<<1, 32>>>(out);
}

// round 8
// speedup vs baseline: 6.9761x; 1.3293x over previous
#include <cuda_runtime.h>
#include <math.h>

#define A_ 10
#define B_ 1024
#define Y_ 94
#define R_ 256
#define H_ 128
#define G_ 768
#define T_ 50
#define IN_ 350
#define FS_ 0.1f

#define BTILE 74
#define NTILES 14      // 14*74 = 1036 >= 1024
#define ROWPAD 80      // 16 warps * RT 5 rows ; also 5 m16 tiles
#define RT 5
#define NTHREADS 512
#define ES 356         // enc row stride (float4-aligned)
#define DS 132         // d/e row stride

#define NK8_I 44       // gi k8 tiles: 12 (y, padded 96) + 32 (h)
#define NK8_H 32       // gh k8 tiles

typedef unsigned long long ull;

__device__ __forceinline__ ull pack2(float x, float y) {
    ull r; asm("mov.b64 %0, {%1, %2};" : "=l"(r) : "f"(x), "f"(y)); return r;
}
__device__ __forceinline__ ull dup2(float x) {
    ull r; asm("mov.b64 %0, {%1, %1};" : "=l"(r) : "f"(x)); return r;
}
__device__ __forceinline__ ull fma2(ull a, ull b, ull c) {
    ull d; asm("fma.rn.f32x2 %0, %1, %2, %3;" : "=l"(d) : "l"(a), "l"(b), "l"(c)); return d;
}
__device__ __forceinline__ float2 unpk2(ull v) {
    float2 f; asm("mov.b64 {%0, %1}, %2;" : "=f"(f.x), "=f"(f.y) : "l"(v)); return f;
}
__device__ __forceinline__ unsigned f2tf(float f) {
    unsigned r; asm("cvt.rna.tf32.f32 %0, %1;" : "=r"(r) : "f"(f)); return r;
}
__device__ __forceinline__ void mma8(float* d, const unsigned* A, unsigned b0, unsigned b1) {
    asm volatile("mma.sync.aligned.m16n8k8.row.col.f32.tf32.tf32.f32 "
        "{%0,%1,%2,%3}, {%4,%5,%6,%7}, {%8,%9}, {%0,%1,%2,%3};"
        : "+f"(d[0]), "+f"(d[1]), "+f"(d[2]), "+f"(d[3])
        : "r"(A[0]), "r"(A[1]), "r"(A[2]), "r"(A[3]), "r"(b0), "r"(b1));
}

// scratch (no cudaMalloc allowed)
__device__ __align__(16) float g_h[A_ * B_ * R_];
__device__ __align__(16) float g_Wim[A_ * 32 * NK8_I * 3 * 64];  // mma-frag packed, tf32
__device__ __align__(16) float g_Whm[A_ * 32 * NK8_H * 3 * 64];  // mma-frag packed, tf32
__device__ __align__(16) float g_d1T[A_ * R_ * H_];              // [a][k][j]
__device__ __align__(16) float g_d2T[A_ * H_ * H_];              // [a][k][j]
__device__ double g_acc[3];

// ---- single prep kernel: init + all weight repacks (keeps launch count low) ----
__global__ void prep_kernel(const float* __restrict__ W_ih, const float* __restrict__ W_hh,
                            const float* __restrict__ d1w,  const float* __restrict__ d2w) {
    const int stride = gridDim.x * blockDim.x;
    const int tid0 = blockIdx.x * blockDim.x + threadIdx.x;

    for (int i = tid0; i < A_ * B_ * R_; i += stride) g_h[i] = 0.f;
    if (tid0 < 3) g_acc[tid0] = 0.0;

    // gi weights -> per-(c, k8, gate) 8x8 B-fragments: lane l holds (b0,b1) at +2l
    const int NWI = A_ * 32 * NK8_I * 3 * 64;
    for (int i = tid0; i < NWI; i += stride) {
        int s = i & 1, l = (i >> 1) & 31;
        int r = i >> 6;
        int g = r % 3; r /= 3;
        int k8 = r % NK8_I; r /= NK8_I;
        int c = r % 32; int a = r / 32;
        int j = g * 256 + c * 8 + (l >> 2);
        float v = 0.f;
        if (k8 < 12) {
            int k = k8 * 8 + (l & 3) + 4 * s;
            if (k < Y_) v = W_ih[((size_t)a * G_ + j) * IN_ + k];
        } else {
            int k = Y_ + (k8 - 12) * 8 + (l & 3) + 4 * s;
            v = W_ih[((size_t)a * G_ + j) * IN_ + k];
        }
        g_Wim[i] = __uint_as_float(f2tf(v));
    }
    // gh weights
    const int NWH = A_ * 32 * NK8_H * 3 * 64;
    for (int i = tid0; i < NWH; i += stride) {
        int s = i & 1, l = (i >> 1) & 31;
        int r = i >> 6;
        int g = r % 3; r /= 3;
        int k8 = r % NK8_H; r /= NK8_H;
        int c = r % 32; int a = r / 32;
        int j = g * 256 + c * 8 + (l >> 2);
        int k = k8 * 8 + (l & 3) + 4 * s;
        g_Whm[i] = __uint_as_float(f2tf(W_hh[((size_t)a * G_ + j) * R_ + k]));
    }
    // d-net transposes (fp32 FFMA2 path)
    for (int i = tid0; i < A_ * R_ * H_; i += stride) {
        int j = i % H_;
        int r = i / H_;
        int k = r % R_;
        int a = r / R_;
        g_d1T[i] = d1w[((size_t)a * H_ + j) * R_ + k];
    }
    for (int i = tid0; i < A_ * H_ * H_; i += stride) {
        int j = i % H_;
        int r = i / H_;
        int k = r % H_;
        int a = r / H_;
        g_d2T[i] = d2w[((size_t)a * H_ + j) * H_ + k];
    }
}

// ep term is RNN-independent: fully parallel over (t, a, b)
__global__ void ep_kernel(const float* __restrict__ states) {
    int idx = blockIdx.x * blockDim.x + threadIdx.x;
    double e = 0.0;
    if (idx < T_ * A_ * B_) {
        int t = idx / (A_ * B_);
        int r = idx - t * (A_ * B_);
        int a = r >> 10;
        int b = r & 1023;
        size_t base = (((size_t)t * A_ + a) * B_ + b) * Y_ + 4 * a;
        float f0 = states[base + 0], f1 = states[base + 1];
        float f2 = states[base + 2], f3 = states[base + 3];
        size_t base1 = base + (size_t)A_ * B_ * Y_;
        float g0 = states[base1 + 0], g1 = states[base1 + 1];
        float d0 = f0 + f2 * FS_ - g0;
        float d1 = f1 + f3 * FS_ - g1;
        e = sqrt((double)d0 * d0 + (double)d1 * d1);
    }
    #pragma unroll
    for (int o = 16; o; o >>= 1) e += __shfl_down_sync(0xffffffffu, e, o);
    if ((threadIdx.x & 31) == 0) atomicAdd(&g_acc[1], e);
}

__global__ __launch_bounds__(NTHREADS) void step_kernel(
    const float* __restrict__ states,
    const float* __restrict__ b_ih, const float* __restrict__ b_hh,
    const float* __restrict__ d1b,  const float* __restrict__ d2b,
    const float* __restrict__ mw,   const float* __restrict__ mb,
    const float* __restrict__ sw,   const float* __restrict__ sb,
    int t)
{
    extern __shared__ float sm[];
    float* enc_s = sm;                         // ROWPAD*ES  [y(96 padded)|h(256)], tf32-rounded
    float* d_s   = enc_s + ROWPAD * ES;        // ROWPAD*DS
    float* e_s   = d_s   + ROWPAD * DS;        // ROWPAD*DS
    float* ms_s  = e_s   + ROWPAD * DS;        // ROWPAD*4

    const int a     = blockIdx.y;
    const int row0  = blockIdx.x * BTILE;
    const int nrows = min(BTILE, B_ - row0);
    const int tid   = threadIdx.x;
    const int tx    = tid & 31;
    const int ty    = tid >> 5;     // warp 0..15
    const int cp    = 2 * tx;

    // ---- stage enc = [y | 0 0 | h], tf32-rounded (mma A operand) ----
    const float* hg = g_h + ((size_t)a * B_ + row0) * R_;
    for (int i = tid; i < ROWPAD * R_; i += NTHREADS) {
        int r = i >> 8, k = i & 255;
        enc_s[r * ES + 96 + k] = (r < nrows) ? __uint_as_float(f2tf(hg[(size_t)r * R_ + k])) : 0.f;
    }
    const float* yg = states + (((size_t)t * A_ + a) * B_ + row0) * Y_;
    for (int i = tid; i < ROWPAD * 96; i += NTHREADS) {
        int r = i / 96, k = i - r * 96;
        enc_s[r * ES + k] = (r < nrows && k < Y_) ? __uint_as_float(f2tf(yg[(size_t)r * Y_ + k])) : 0.f;
    }
    __syncthreads();

    // ---- D1 (FFMA2): col-pairs (cp, cp+1) and (cp+64, cp+65), rows ty+16i ----
    {
        ull acc[RT][2];
        {
            ull b0 = *reinterpret_cast<const ull*>(&d1b[a * H_ + cp]);
            ull b1 = *reinterpret_cast<const ull*>(&d1b[a * H_ + cp + 64]);
            #pragma unroll
            for (int i = 0; i < RT; i++) { acc[i][0] = b0; acc[i][1] = b1; }
        }
        const float* W = g_d1T + (size_t)a * R_ * H_;
        for (int k = 0; k < R_; k += 4) {
            float4 hv[RT];
            #pragma unroll
            for (int i = 0; i < RT; i++)
                hv[i] = *reinterpret_cast<const float4*>(&enc_s[(ty + 16 * i) * ES + 96 + k]);
            #pragma unroll
            for (int kk = 0; kk < 4; kk++) {
                const float* Wr = W + (size_t)(k + kk) * H_;
                ull w0 = *reinterpret_cast<const ull*>(&Wr[cp]);
                ull w1 = *reinterpret_cast<const ull*>(&Wr[cp + 64]);
                #pragma unroll
                for (int i = 0; i < RT; i++) {
                    ull hh = dup2(reinterpret_cast<const float*>(&hv[i])[kk]);
                    acc[i][0] = fma2(hh, w0, acc[i][0]);
                    acc[i][1] = fma2(hh, w1, acc[i][1]);
                }
            }
        }
        #pragma unroll
        for (int i = 0; i < RT; i++) {
            int r = ty + 16 * i;
            #pragma unroll
            for (int jj = 0; jj < 2; jj++) {
                float2 v = unpk2(acc[i][jj]);
                v.x = fmaxf(v.x, 0.f); v.y = fmaxf(v.y, 0.f);
                *reinterpret_cast<ull*>(&d_s[r * DS + cp + 64 * jj]) = pack2(v.x, v.y);
            }
        }
    }
    __syncthreads();

    // ---- D2 (FFMA2) ----
    {
        ull acc[RT][2];
        {
            ull b0 = *reinterpret_cast<const ull*>(&d2b[a * H_ + cp]);
            ull b1 = *reinterpret_cast<const ull*>(&d2b[a * H_ + cp + 64]);
            #pragma unroll
            for (int i = 0; i < RT; i++) { acc[i][0] = b0; acc[i][1] = b1; }
        }
        const float* W = g_d2T + (size_t)a * H_ * H_;
        for (int k = 0; k < H_; k += 4) {
            float4 dv[RT];
            #pragma unroll
            for (int i = 0; i < RT; i++)
                dv[i] = *reinterpret_cast<const float4*>(&d_s[(ty + 16 * i) * DS + k]);
            #pragma unroll
            for (int kk = 0; kk < 4; kk++) {
                const float* Wr = W + (size_t)(k + kk) * H_;
                ull w0 = *reinterpret_cast<const ull*>(&Wr[cp]);
                ull w1 = *reinterpret_cast<const ull*>(&Wr[cp + 64]);
                #pragma unroll
                for (int i = 0; i < RT; i++) {
                    ull hh = dup2(reinterpret_cast<const float*>(&dv[i])[kk]);
                    acc[i][0] = fma2(hh, w0, acc[i][0]);
                    acc[i][1] = fma2(hh, w1, acc[i][1]);
                }
            }
        }
        #pragma unroll
        for (int i = 0; i < RT; i++) {
            int r = ty + 16 * i;
            #pragma unroll
            for (int jj = 0; jj < 2; jj++) {
                float2 v = unpk2(acc[i][jj]);
                v.x = fmaxf(v.x, 0.f); v.y = fmaxf(v.y, 0.f);
                *reinterpret_cast<ull*>(&e_s[r * DS + cp + 64 * jj]) = pack2(v.x, v.y);
            }
        }
    }
    __syncthreads();

    // ---- mean / std heads ----
    for (int task = tid; task < nrows * 4; task += NTHREADS) {
        int r = task >> 2, o = task & 3;
        const float* W = (o < 2) ? (mw + ((size_t)a * 2 + o) * H_)
                                 : (sw + ((size_t)a * 2 + (o - 2)) * H_);
        float acc = (o < 2) ? mb[a * 2 + o] : sb[a * 2 + o - 2];
        for (int k = 0; k < H_; k++) acc += e_s[r * DS + k] * W[k];
        if (o >= 2)
            acc = fmaxf(acc, 0.f) + log1pf(expf(-fabsf(acc)));
        ms_s[r * 4 + o] = acc;
    }
    __syncthreads();

    // ---- per-row NLL + ev ----
    {
        double lsum = 0.0, esum = 0.0;
        if (tid < nrows) {
            int b = row0 + tid;
            size_t xb = (((size_t)(t + 1) * A_ + a) * B_ + b) * Y_ + 4 * a;
            float x0 = states[xb + 2], x1 = states[xb + 3];
            float m0 = ms_s[tid * 4 + 0], m1 = ms_s[tid * 4 + 1];
            float s0 = ms_s[tid * 4 + 2], s1 = ms_s[tid * 4 + 3];
            float z0 = (x0 - m0) / s0, z1 = (x1 - m1) / s1;
            const double L2PI = 1.8378770664093453;
            lsum = 0.5 * ((double)(z0 * z0) + (double)(z1 * z1)
                 + 2.0 * ((double)logf(s0) + (double)logf(s1)) + 2.0 * L2PI);
            float dm0 = m0 - x0, dm1 = m1 - x1;
            esum = sqrt((double)dm0 * dm0 + (double)dm1 * dm1);
        }
        #pragma unroll
        for (int o = 16; o; o >>= 1) {
            lsum += __shfl_down_sync(0xffffffffu, lsum, o);
            esum += __shfl_down_sync(0xffffffffu, esum, o);
        }
        if ((tid & 31) == 0) {
            atomicAdd(&g_acc[0], lsum);
            atomicAdd(&g_acc[2], esum);
        }
    }

    // ---- GRU via tf32 mma.sync: unit = (m16-tile, h-col8) ----
    {
        const int lane = tx;
        const int tg   = lane & 3;    // thread-in-group (k / paired col idx)
        const int gid  = lane >> 2;   // group id (row idx)
        #pragma unroll 1
        for (int u = 0; u < 10; u++) {
            int unit = ty + 16 * u;          // 0..159
            int m0 = (unit % 5) * 16;
            int c  = unit / 5;               // 0..31
            int j0 = c * 8;
            const float2* Wib = reinterpret_cast<const float2*>(
                g_Wim + ((size_t)(a * 32 + c) * NK8_I * 3) * 64);
            const float2* Whb = reinterpret_cast<const float2*>(
                g_Whm + ((size_t)(a * 32 + c) * NK8_H * 3) * 64);

            float air[4], aiz[4], ain[4], ahr[4], ahz[4], ahn[4];
            {
                int jb = j0 + 2 * tg;
                float2 br = *reinterpret_cast<const float2*>(&b_ih[a * G_ + jb]);
                float2 bz = *reinterpret_cast<const float2*>(&b_ih[a * G_ + 256 + jb]);
                float2 bn = *reinterpret_cast<const float2*>(&b_ih[a * G_ + 512 + jb]);
                float2 cr = *reinterpret_cast<const float2*>(&b_hh[a * G_ + jb]);
                float2 cz = *reinterpret_cast<const float2*>(&b_hh[a * G_ + 256 + jb]);
                float2 cn = *reinterpret_cast<const float2*>(&b_hh[a * G_ + 512 + jb]);
                air[0] = br.x; air[1] = br.y; air[2] = br.x; air[3] = br.y;
                aiz[0] = bz.x; aiz[1] = bz.y; aiz[2] = bz.x; aiz[3] = bz.y;
                ain[0] = bn.x; ain[1] = bn.y; ain[2] = bn.x; ain[3] = bn.y;
                ahr[0] = cr.x; ahr[1] = cr.y; ahr[2] = cr.x; ahr[3] = cr.y;
                ahz[0] = cz.x; ahz[1] = cz.y; ahz[2] = cz.x; ahz[3] = cz.y;
                ahn[0] = cn.x; ahn[1] = cn.y; ahn[2] = cn.x; ahn[3] = cn.y;
            }

            // y region: 12 k8, gi only
            for (int k8 = 0; k8 < 12; k8++) {
                unsigned Af[4];
                int kc = k8 * 8 + tg;
                Af[0] = __float_as_uint(enc_s[(m0 + gid) * ES + kc]);
                Af[1] = __float_as_uint(enc_s[(m0 + gid + 8) * ES + kc]);
                Af[2] = __float_as_uint(enc_s[(m0 + gid) * ES + kc + 4]);
                Af[3] = __float_as_uint(enc_s[(m0 + gid + 8) * ES + kc + 4]);
                float2 wr = Wib[(k8 * 3 + 0) * 32 + lane];
                float2 wz = Wib[(k8 * 3 + 1) * 32 + lane];
                float2 wn = Wib[(k8 * 3 + 2) * 32 + lane];
                mma8(air, Af, __float_as_uint(wr.x), __float_as_uint(wr.y));
                mma8(aiz, Af, __float_as_uint(wz.x), __float_as_uint(wz.y));
                mma8(ain, Af, __float_as_uint(wn.x), __float_as_uint(wn.y));
            }
            // h region: 32 k8, gi and gh share the A fragment
            for (int k8 = 0; k8 < 32; k8++) {
                unsigned Af[4];
                int kc = 96 + k8 * 8 + tg;
                Af[0] = __float_as_uint(enc_s[(m0 + gid) * ES + kc]);
                Af[1] = __float_as_uint(enc_s[(m0 + gid + 8) * ES + kc]);
                Af[2] = __float_as_uint(enc_s[(m0 + gid) * ES + kc + 4]);
                Af[3] = __float_as_uint(enc_s[(m0 + gid + 8) * ES + kc + 4]);
                float2 wir = Wib[((12 + k8) * 3 + 0) * 32 + lane];
                float2 wiz = Wib[((12 + k8) * 3 + 1) * 32 + lane];
                float2 win = Wib[((12 + k8) * 3 + 2) * 32 + lane];
                float2 whr = Whb[(k8 * 3 + 0) * 32 + lane];
                float2 whz = Whb[(k8 * 3 + 1) * 32 + lane];
                float2 whn = Whb[(k8 * 3 + 2) * 32 + lane];
                mma8(air, Af, __float_as_uint(wir.x), __float_as_uint(wir.y));
                mma8(aiz, Af, __float_as_uint(wiz.x), __float_as_uint(wiz.y));
                mma8(ain, Af, __float_as_uint(win.x), __float_as_uint(win.y));
                mma8(ahr, Af, __float_as_uint(whr.x), __float_as_uint(whr.y));
                mma8(ahz, Af, __float_as_uint(whz.x), __float_as_uint(whz.y));
                mma8(ahn, Af, __float_as_uint(whn.x), __float_as_uint(whn.y));
            }
            // epilogue: gates + h update (hold read fp32 from global, exact carry)
            #pragma unroll
            for (int half = 0; half < 2; half++) {
                int r = m0 + gid + 8 * half;
                int e0 = 2 * half, e1 = e0 + 1;
                if (r < nrows) {
                    int jb = j0 + 2 * tg;
                    float* hrow = &g_h[((size_t)a * B_ + row0 + r) * R_ + jb];
                    float2 hold = *reinterpret_cast<const float2*>(hrow);
                    float rg0 = 1.f / (1.f + expf(-(air[e0] + ahr[e0])));
                    float rg1 = 1.f / (1.f + expf(-(air[e1] + ahr[e1])));
                    float zg0 = 1.f / (1.f + expf(-(aiz[e0] + ahz[e0])));
                    float zg1 = 1.f / (1.f + expf(-(aiz[e1] + ahz[e1])));
                    float ng0 = tanhf(ain[e0] + rg0 * ahn[e0]);
                    float ng1 = tanhf(ain[e1] + rg1 * ahn[e1]);
                    float h0 = (1.f - zg0) * ng0 + zg0 * hold.x;
                    float h1 = (1.f - zg1) * ng1 + zg1 * hold.y;
                    *reinterpret_cast<ull*>(hrow) = pack2(h0, h1);
                }
            }
        }
    }
}

__global__ void final_kernel(float* out) {
    if (threadIdx.x == 0) {
        const double denom = (double)T_ * A_;
        out[0] = (float)(g_acc[0] / denom);
        out[1] = (float)(g_acc[1] / denom);
        out[2] = (float)(g_acc[2] / denom);
    }
}

extern "C" void kernel_launch(void* const* d_in, const int* in_sizes, int n_in,
                              void* d_out, int out_size) {
    const float* states = (const float*)d_in[0];
    const float* W_ih   = (const float*)d_in[1];
    const float* W_hh   = (const float*)d_in[2];
    const float* b_ih   = (const float*)d_in[3];
    const float* b_hh   = (const float*)d_in[4];
    const float* d1w    = (const float*)d_in[5];
    const float* d1b    = (const float*)d_in[6];
    const float* d2w    = (const float*)d_in[7];
    const float* d2b    = (const float*)d_in[8];
    const float* mw     = (const float*)d_in[9];
    const float* mb     = (const float*)d_in[10];
    const float* sw     = (const float*)d_in[11];
    const float* sb     = (const float*)d_in[12];
    float* out = (float*)d_out;

    const size_t SMEM = (size_t)ROWPAD * (ES + DS + DS + 4) * sizeof(float); // 199,680 B
    cudaFuncSetAttribute(step_kernel, cudaFuncAttributeMaxDynamicSharedMemorySize, (int)SMEM);

    prep_kernel<<<1024, 256>>>(W_ih, W_hh, d1w, d2w);
    ep_kernel<<<(T_ * A_ * B_ + 255) / 256, 256>>>(states);

    dim3 grid(NTILES, A_);
    for (int t = 0; t < T_; t++) {
        step_kernel<<<grid, NTHREADS, SMEM>>>(states, b_ih, b_hh,
                                              d1b, d2b, mw, mb, sw, sb, t);
    }
    final_kernel<<<1, 32>>>(out);
}

// round 9
// speedup vs baseline: 12.7220x; 1.8236x over previous
#include <cuda_runtime.h>
#include <math.h>

#define A_ 10
#define B_ 1024
#define Y_ 94
#define R_ 256
#define H_ 128
#define G_ 768
#define T_ 50
#define IN_ 350
#define FS_ 0.1f

#define BTILE 74
#define NTILES 14      // 14*74 = 1036 >= 1024
#define ROWPAD 80      // 16 warps * RT 5 rows ; 5 m16 tiles
#define RT 5
#define NTHREADS 512
#define ES 356         // enc row stride (float4-aligned)
#define DS 132         // d/e row stride

#define NK8_I 44       // gi k8 tiles: 12 (y, padded 96) + 32 (h)
#define NK8_H 32       // gh k8 tiles

typedef unsigned long long ull;

__device__ __forceinline__ ull pack2(float x, float y) {
    ull r; asm("mov.b64 %0, {%1, %2};" : "=l"(r) : "f"(x), "f"(y)); return r;
}
__device__ __forceinline__ ull dup2(float x) {
    ull r; asm("mov.b64 %0, {%1, %1};" : "=l"(r) : "f"(x)); return r;
}
__device__ __forceinline__ ull fma2(ull a, ull b, ull c) {
    ull d; asm("fma.rn.f32x2 %0, %1, %2, %3;" : "=l"(d) : "l"(a), "l"(b), "l"(c)); return d;
}
__device__ __forceinline__ float2 unpk2(ull v) {
    float2 f; asm("mov.b64 {%0, %1}, %2;" : "=f"(f.x), "=f"(f.y) : "l"(v)); return f;
}
__device__ __forceinline__ unsigned f2tf(float f) {
    unsigned r; asm("cvt.rna.tf32.f32 %0, %1;" : "=r"(r) : "f"(f)); return r;
}
__device__ __forceinline__ void mma8(float* d, const unsigned* A, unsigned b0, unsigned b1) {
    asm volatile("mma.sync.aligned.m16n8k8.row.col.f32.tf32.tf32.f32 "
        "{%0,%1,%2,%3}, {%4,%5,%6,%7}, {%8,%9}, {%0,%1,%2,%3};"
        : "+f"(d[0]), "+f"(d[1]), "+f"(d[2]), "+f"(d[3])
        : "r"(A[0]), "r"(A[1]), "r"(A[2]), "r"(A[3]), "r"(b0), "r"(b1));
}

// scratch (no cudaMalloc allowed)
__device__ __align__(16) float g_h[A_ * B_ * R_];
__device__ __align__(16) float g_Wim[A_ * 32 * NK8_I * 3 * 64];  // mma-frag packed, tf32
__device__ __align__(16) float g_Whm[A_ * 32 * NK8_H * 3 * 64];  // mma-frag packed, tf32
__device__ __align__(16) float g_d1T[A_ * R_ * H_];              // [a][k][j]
__device__ __align__(16) float g_d2T[A_ * H_ * H_];              // [a][k][j]
__device__ double g_acc[3];

// ---- single prep kernel: init + all weight repacks ----
__global__ void prep_kernel(const float* __restrict__ W_ih, const float* __restrict__ W_hh,
                            const float* __restrict__ d1w,  const float* __restrict__ d2w) {
    const int stride = gridDim.x * blockDim.x;
    const int tid0 = blockIdx.x * blockDim.x + threadIdx.x;

    for (int i = tid0; i < A_ * B_ * R_; i += stride) g_h[i] = 0.f;
    if (tid0 < 3) g_acc[tid0] = 0.0;

    // gi weights -> per-(c, k8, gate) 8x8 B-fragments: lane l holds (b0,b1) at +2l
    const int NWI = A_ * 32 * NK8_I * 3 * 64;
    for (int i = tid0; i < NWI; i += stride) {
        int s = i & 1, l = (i >> 1) & 31;
        int r = i >> 6;
        int g = r % 3; r /= 3;
        int k8 = r % NK8_I; r /= NK8_I;
        int c = r % 32; int a = r / 32;
        int j = g * 256 + c * 8 + (l >> 2);
        float v = 0.f;
        if (k8 < 12) {
            int k = k8 * 8 + (l & 3) + 4 * s;
            if (k < Y_) v = W_ih[((size_t)a * G_ + j) * IN_ + k];
        } else {
            int k = Y_ + (k8 - 12) * 8 + (l & 3) + 4 * s;
            v = W_ih[((size_t)a * G_ + j) * IN_ + k];
        }
        g_Wim[i] = __uint_as_float(f2tf(v));
    }
    // gh weights
    const int NWH = A_ * 32 * NK8_H * 3 * 64;
    for (int i = tid0; i < NWH; i += stride) {
        int s = i & 1, l = (i >> 1) & 31;
        int r = i >> 6;
        int g = r % 3; r /= 3;
        int k8 = r % NK8_H; r /= NK8_H;
        int c = r % 32; int a = r / 32;
        int j = g * 256 + c * 8 + (l >> 2);
        int k = k8 * 8 + (l & 3) + 4 * s;
        g_Whm[i] = __uint_as_float(f2tf(W_hh[((size_t)a * G_ + j) * R_ + k]));
    }
    // d-net transposes (fp32 FFMA2 path)
    for (int i = tid0; i < A_ * R_ * H_; i += stride) {
        int j = i % H_;
        int r = i / H_;
        int k = r % R_;
        int a = r / R_;
        g_d1T[i] = d1w[((size_t)a * H_ + j) * R_ + k];
    }
    for (int i = tid0; i < A_ * H_ * H_; i += stride) {
        int j = i % H_;
        int r = i / H_;
        int k = r % H_;
        int a = r / H_;
        g_d2T[i] = d2w[((size_t)a * H_ + j) * H_ + k];
    }
}

// ep term is RNN-independent: fully parallel over (t, a, b)
__global__ void ep_kernel(const float* __restrict__ states) {
    int idx = blockIdx.x * blockDim.x + threadIdx.x;
    double e = 0.0;
    if (idx < T_ * A_ * B_) {
        int t = idx / (A_ * B_);
        int r = idx - t * (A_ * B_);
        int a = r >> 10;
        int b = r & 1023;
        size_t base = (((size_t)t * A_ + a) * B_ + b) * Y_ + 4 * a;
        float f0 = states[base + 0], f1 = states[base + 1];
        float f2 = states[base + 2], f3 = states[base + 3];
        size_t base1 = base + (size_t)A_ * B_ * Y_;
        float g0 = states[base1 + 0], g1 = states[base1 + 1];
        float d0 = f0 + f2 * FS_ - g0;
        float d1 = f1 + f3 * FS_ - g1;
        e = sqrt((double)d0 * d0 + (double)d1 * d1);
    }
    #pragma unroll
    for (int o = 16; o; o >>= 1) e += __shfl_down_sync(0xffffffffu, e, o);
    if ((threadIdx.x & 31) == 0) atomicAdd(&g_acc[1], e);
}

__global__ __launch_bounds__(NTHREADS) void step_kernel(
    const float* __restrict__ states,
    const float* __restrict__ b_ih, const float* __restrict__ b_hh,
    const float* __restrict__ d1b,  const float* __restrict__ d2b,
    const float* __restrict__ mw,   const float* __restrict__ mb,
    const float* __restrict__ sw,   const float* __restrict__ sb,
    int t)
{
    extern __shared__ float sm[];
    float* enc_s = sm;                         // ROWPAD*ES  [y(96 padded)|h(256)], tf32-rounded
    float* d_s   = enc_s + ROWPAD * ES;        // ROWPAD*DS
    float* e_s   = d_s   + ROWPAD * DS;        // ROWPAD*DS
    float* ms_s  = e_s   + ROWPAD * DS;        // ROWPAD*4

    const int a     = blockIdx.y;
    const int row0  = blockIdx.x * BTILE;
    const int nrows = min(BTILE, B_ - row0);
    const int tid   = threadIdx.x;
    const int tx    = tid & 31;
    const int ty    = tid >> 5;     // warp 0..15
    const int cp    = 2 * tx;

    // ---- stage enc = [y | 0 0 | h], tf32-rounded (mma A operand) ----
    const float* hg = g_h + ((size_t)a * B_ + row0) * R_;
    for (int i = tid; i < ROWPAD * R_; i += NTHREADS) {
        int r = i >> 8, k = i & 255;
        enc_s[r * ES + 96 + k] = (r < nrows) ? __uint_as_float(f2tf(hg[(size_t)r * R_ + k])) : 0.f;
    }
    const float* yg = states + (((size_t)t * A_ + a) * B_ + row0) * Y_;
    for (int i = tid; i < ROWPAD * 96; i += NTHREADS) {
        int r = i / 96, k = i - r * 96;
        enc_s[r * ES + k] = (r < nrows && k < Y_) ? __uint_as_float(f2tf(yg[(size_t)r * Y_ + k])) : 0.f;
    }
    __syncthreads();

    // ---- D1 (FFMA2) ----
    {
        ull acc[RT][2];
        {
            ull b0 = *reinterpret_cast<const ull*>(&d1b[a * H_ + cp]);
            ull b1 = *reinterpret_cast<const ull*>(&d1b[a * H_ + cp + 64]);
            #pragma unroll
            for (int i = 0; i < RT; i++) { acc[i][0] = b0; acc[i][1] = b1; }
        }
        const float* W = g_d1T + (size_t)a * R_ * H_;
        for (int k = 0; k < R_; k += 4) {
            float4 hv[RT];
            #pragma unroll
            for (int i = 0; i < RT; i++)
                hv[i] = *reinterpret_cast<const float4*>(&enc_s[(ty + 16 * i) * ES + 96 + k]);
            #pragma unroll
            for (int kk = 0; kk < 4; kk++) {
                const float* Wr = W + (size_t)(k + kk) * H_;
                ull w0 = *reinterpret_cast<const ull*>(&Wr[cp]);
                ull w1 = *reinterpret_cast<const ull*>(&Wr[cp + 64]);
                #pragma unroll
                for (int i = 0; i < RT; i++) {
                    ull hh = dup2(reinterpret_cast<const float*>(&hv[i])[kk]);
                    acc[i][0] = fma2(hh, w0, acc[i][0]);
                    acc[i][1] = fma2(hh, w1, acc[i][1]);
                }
            }
        }
        #pragma unroll
        for (int i = 0; i < RT; i++) {
            int r = ty + 16 * i;
            #pragma unroll
            for (int jj = 0; jj < 2; jj++) {
                float2 v = unpk2(acc[i][jj]);
                v.x = fmaxf(v.x, 0.f); v.y = fmaxf(v.y, 0.f);
                *reinterpret_cast<ull*>(&d_s[r * DS + cp + 64 * jj]) = pack2(v.x, v.y);
            }
        }
    }
    __syncthreads();

    // ---- D2 (FFMA2) ----
    {
        ull acc[RT][2];
        {
            ull b0 = *reinterpret_cast<const ull*>(&d2b[a * H_ + cp]);
            ull b1 = *reinterpret_cast<const ull*>(&d2b[a * H_ + cp + 64]);
            #pragma unroll
            for (int i = 0; i < RT; i++) { acc[i][0] = b0; acc[i][1] = b1; }
        }
        const float* W = g_d2T + (size_t)a * H_ * H_;
        for (int k = 0; k < H_; k += 4) {
            float4 dv[RT];
            #pragma unroll
            for (int i = 0; i < RT; i++)
                dv[i] = *reinterpret_cast<const float4*>(&d_s[(ty + 16 * i) * DS + k]);
            #pragma unroll
            for (int kk = 0; kk < 4; kk++) {
                const float* Wr = W + (size_t)(k + kk) * H_;
                ull w0 = *reinterpret_cast<const ull*>(&Wr[cp]);
                ull w1 = *reinterpret_cast<const ull*>(&Wr[cp + 64]);
                #pragma unroll
                for (int i = 0; i < RT; i++) {
                    ull hh = dup2(reinterpret_cast<const float*>(&dv[i])[kk]);
                    acc[i][0] = fma2(hh, w0, acc[i][0]);
                    acc[i][1] = fma2(hh, w1, acc[i][1]);
                }
            }
        }
        #pragma unroll
        for (int i = 0; i < RT; i++) {
            int r = ty + 16 * i;
            #pragma unroll
            for (int jj = 0; jj < 2; jj++) {
                float2 v = unpk2(acc[i][jj]);
                v.x = fmaxf(v.x, 0.f); v.y = fmaxf(v.y, 0.f);
                *reinterpret_cast<ull*>(&e_s[r * DS + cp + 64 * jj]) = pack2(v.x, v.y);
            }
        }
    }
    __syncthreads();

    // ---- mean / std heads ----
    for (int task = tid; task < nrows * 4; task += NTHREADS) {
        int r = task >> 2, o = task & 3;
        const float* W = (o < 2) ? (mw + ((size_t)a * 2 + o) * H_)
                                 : (sw + ((size_t)a * 2 + (o - 2)) * H_);
        float acc = (o < 2) ? mb[a * 2 + o] : sb[a * 2 + o - 2];
        for (int k = 0; k < H_; k++) acc += e_s[r * DS + k] * W[k];
        if (o >= 2)
            acc = fmaxf(acc, 0.f) + log1pf(expf(-fabsf(acc)));
        ms_s[r * 4 + o] = acc;
    }
    __syncthreads();

    // ---- per-row NLL + ev ----
    {
        double lsum = 0.0, esum = 0.0;
        if (tid < nrows) {
            int b = row0 + tid;
            size_t xb = (((size_t)(t + 1) * A_ + a) * B_ + b) * Y_ + 4 * a;
            float x0 = states[xb + 2], x1 = states[xb + 3];
            float m0 = ms_s[tid * 4 + 0], m1 = ms_s[tid * 4 + 1];
            float s0 = ms_s[tid * 4 + 2], s1 = ms_s[tid * 4 + 3];
            float z0 = (x0 - m0) / s0, z1 = (x1 - m1) / s1;
            const double L2PI = 1.8378770664093453;
            lsum = 0.5 * ((double)(z0 * z0) + (double)(z1 * z1)
                 + 2.0 * ((double)logf(s0) + (double)logf(s1)) + 2.0 * L2PI);
            float dm0 = m0 - x0, dm1 = m1 - x1;
            esum = sqrt((double)dm0 * dm0 + (double)dm1 * dm1);
        }
        #pragma unroll
        for (int o = 16; o; o >>= 1) {
            lsum += __shfl_down_sync(0xffffffffu, lsum, o);
            esum += __shfl_down_sync(0xffffffffu, esum, o);
        }
        if ((tid & 31) == 0) {
            atomicAdd(&g_acc[0], lsum);
            atomicAdd(&g_acc[2], esum);
        }
    }

    // ---- GRU via tf32 mma.sync ----
    // unit = (m32-group, col8-group): 3 m-groups x 32 c = 96 units, 6 per warp.
    // Weight fragments are loaded once per k8 and reused for BOTH m16 tiles of
    // the group; next iteration's weights are prefetched before this
    // iteration's mmas so mmas never wait on an in-flight LDG.
    {
        const int lane = tx;
        const int tg   = lane & 3;    // thread-in-group
        const int gid  = lane >> 2;   // group id (row within tile)
        #pragma unroll 1
        for (int u = 0; u < 6; u++) {
            int unit = ty + 16 * u;          // 0..95
            int mg = unit >> 5;              // 0..2
            int c  = unit & 31;
            int m0 = mg * 32;                // tile0 rows m0.., tile1 rows m0+16..
            const bool two = (mg < 2);       // mg==2 covers rows 64..79 only
            int j0 = c * 8;
            const float2* Wib = reinterpret_cast<const float2*>(
                g_Wim + ((size_t)(a * 32 + c) * NK8_I * 3) * 64);
            const float2* Whb = reinterpret_cast<const float2*>(
                g_Whm + ((size_t)(a * 32 + c) * NK8_H * 3) * 64);

            // acc[tile][gate][4]; gates: 0 ir, 1 iz, 2 in, 3 hr, 4 hz, 5 hn
            float acc0[6][4], acc1[6][4];
            {
                int jb = j0 + 2 * tg;
                float2 bv[6];
                bv[0] = *reinterpret_cast<const float2*>(&b_ih[a * G_ + jb]);
                bv[1] = *reinterpret_cast<const float2*>(&b_ih[a * G_ + 256 + jb]);
                bv[2] = *reinterpret_cast<const float2*>(&b_ih[a * G_ + 512 + jb]);
                bv[3] = *reinterpret_cast<const float2*>(&b_hh[a * G_ + jb]);
                bv[4] = *reinterpret_cast<const float2*>(&b_hh[a * G_ + 256 + jb]);
                bv[5] = *reinterpret_cast<const float2*>(&b_hh[a * G_ + 512 + jb]);
                #pragma unroll
                for (int g = 0; g < 6; g++) {
                    acc0[g][0] = bv[g].x; acc0[g][1] = bv[g].y;
                    acc0[g][2] = bv[g].x; acc0[g][3] = bv[g].y;
                    acc1[g][0] = bv[g].x; acc1[g][1] = bv[g].y;
                    acc1[g][2] = bv[g].x; acc1[g][3] = bv[g].y;
                }
            }

            // ---- y region: 12 k8, 3 gi gates ----
            {
                float2 w[3], wn[3];
                #pragma unroll
                for (int g = 0; g < 3; g++) w[g] = Wib[g * 32 + lane];
                for (int k8 = 0; k8 < 12; k8++) {
                    int k8n = (k8 < 11) ? k8 + 1 : 11;
                    #pragma unroll
                    for (int g = 0; g < 3; g++) wn[g] = Wib[(k8n * 3 + g) * 32 + lane];
                    int kc = k8 * 8 + tg;
                    unsigned A0[4];
                    A0[0] = __float_as_uint(enc_s[(m0 + gid) * ES + kc]);
                    A0[1] = __float_as_uint(enc_s[(m0 + gid + 8) * ES + kc]);
                    A0[2] = __float_as_uint(enc_s[(m0 + gid) * ES + kc + 4]);
                    A0[3] = __float_as_uint(enc_s[(m0 + gid + 8) * ES + kc + 4]);
                    #pragma unroll
                    for (int g = 0; g < 3; g++)
                        mma8(acc0[g], A0, __float_as_uint(w[g].x), __float_as_uint(w[g].y));
                    if (two) {
                        unsigned A1[4];
                        A1[0] = __float_as_uint(enc_s[(m0 + 16 + gid) * ES + kc]);
                        A1[1] = __float_as_uint(enc_s[(m0 + 24 + gid) * ES + kc]);
                        A1[2] = __float_as_uint(enc_s[(m0 + 16 + gid) * ES + kc + 4]);
                        A1[3] = __float_as_uint(enc_s[(m0 + 24 + gid) * ES + kc + 4]);
                        #pragma unroll
                        for (int g = 0; g < 3; g++)
                            mma8(acc1[g], A1, __float_as_uint(w[g].x), __float_as_uint(w[g].y));
                    }
                    #pragma unroll
                    for (int g = 0; g < 3; g++) w[g] = wn[g];
                }
            }

            // ---- h region: 32 k8, all 6 gates share the A fragment ----
            {
                float2 w[6], wn[6];
                #pragma unroll
                for (int g = 0; g < 3; g++) {
                    w[g]     = Wib[(12 * 3 + g) * 32 + lane];
                    w[3 + g] = Whb[g * 32 + lane];
                }
                for (int k8 = 0; k8 < 32; k8++) {
                    int k8n = (k8 < 31) ? k8 + 1 : 31;
                    #pragma unroll
                    for (int g = 0; g < 3; g++) {
                        wn[g]     = Wib[((12 + k8n) * 3 + g) * 32 + lane];
                        wn[3 + g] = Whb[(k8n * 3 + g) * 32 + lane];
                    }
                    int kc = 96 + k8 * 8 + tg;
                    unsigned A0[4];
                    A0[0] = __float_as_uint(enc_s[(m0 + gid) * ES + kc]);
                    A0[1] = __float_as_uint(enc_s[(m0 + gid + 8) * ES + kc]);
                    A0[2] = __float_as_uint(enc_s[(m0 + gid) * ES + kc + 4]);
                    A0[3] = __float_as_uint(enc_s[(m0 + gid + 8) * ES + kc + 4]);
                    #pragma unroll
                    for (int g = 0; g < 6; g++)
                        mma8(acc0[g], A0, __float_as_uint(w[g].x), __float_as_uint(w[g].y));
                    if (two) {
                        unsigned A1[4];
                        A1[0] = __float_as_uint(enc_s[(m0 + 16 + gid) * ES + kc]);
                        A1[1] = __float_as_uint(enc_s[(m0 + 24 + gid) * ES + kc]);
                        A1[2] = __float_as_uint(enc_s[(m0 + 16 + gid) * ES + kc + 4]);
                        A1[3] = __float_as_uint(enc_s[(m0 + 24 + gid) * ES + kc + 4]);
                        #pragma unroll
                        for (int g = 0; g < 6; g++)
                            mma8(acc1[g], A1, __float_as_uint(w[g].x), __float_as_uint(w[g].y));
                    }
                    #pragma unroll
                    for (int g = 0; g < 6; g++) w[g] = wn[g];
                }
            }

            // ---- epilogue: gates + h update for both tiles ----
            #pragma unroll
            for (int tile = 0; tile < 2; tile++) {
                if (tile == 1 && !two) break;
                float (*ac)[4] = tile ? acc1 : acc0;
                int mt = m0 + 16 * tile;
                #pragma unroll
                for (int half = 0; half < 2; half++) {
                    int r = mt + gid + 8 * half;
                    int e0 = 2 * half, e1 = e0 + 1;
                    if (r < nrows) {
                        int jb = j0 + 2 * tg;
                        float* hrow = &g_h[((size_t)a * B_ + row0 + r) * R_ + jb];
                        float2 hold = *reinterpret_cast<const float2*>(hrow);
                        float rg0 = 1.f / (1.f + expf(-(ac[0][e0] + ac[3][e0])));
                        float rg1 = 1.f / (1.f + expf(-(ac[0][e1] + ac[3][e1])));
                        float zg0 = 1.f / (1.f + expf(-(ac[1][e0] + ac[4][e0])));
                        float zg1 = 1.f / (1.f + expf(-(ac[1][e1] + ac[4][e1])));
                        float ng0 = tanhf(ac[2][e0] + rg0 * ac[5][e0]);
                        float ng1 = tanhf(ac[2][e1] + rg1 * ac[5][e1]);
                        float h0 = (1.f - zg0) * ng0 + zg0 * hold.x;
                        float h1 = (1.f - zg1) * ng1 + zg1 * hold.y;
                        *reinterpret_cast<ull*>(hrow) = pack2(h0, h1);
                    }
                }
            }
        }
    }
}

__global__ void final_kernel(float* out) {
    if (threadIdx.x == 0) {
        const double denom = (double)T_ * A_;
        out[0] = (float)(g_acc[0] / denom);
        out[1] = (float)(g_acc[1] / denom);
        out[2] = (float)(g_acc[2] / denom);
    }
}

extern "C" void kernel_launch(void* const* d_in, const int* in_sizes, int n_in,
                              void* d_out, int out_size) {
    const float* states = (const float*)d_in[0];
    const float* W_ih   = (const float*)d_in[1];
    const float* W_hh   = (const float*)d_in[2];
    const float* b_ih   = (const float*)d_in[3];
    const float* b_hh   = (const float*)d_in[4];
    const float* d1w    = (const float*)d_in[5];
    const float* d1b    = (const float*)d_in[6];
    const float* d2w    = (const float*)d_in[7];
    const float* d2b    = (const float*)d_in[8];
    const float* mw     = (const float*)d_in[9];
    const float* mb     = (const float*)d_in[10];
    const float* sw     = (const float*)d_in[11];
    const float* sb     = (const float*)d_in[12];
    float* out = (float*)d_out;

    const size_t SMEM = (size_t)ROWPAD * (ES + DS + DS + 4) * sizeof(float); // 199,680 B
    cudaFuncSetAttribute(step_kernel, cudaFuncAttributeMaxDynamicSharedMemorySize, (int)SMEM);

    prep_kernel<<<1024, 256>>>(W_ih, W_hh, d1w, d2w);
    ep_kernel<<<(T_ * A_ * B_ + 255) / 256, 256>>>(states);

    dim3 grid(NTILES, A_);
    for (int t = 0; t < T_; t++) {
        step_kernel<<<grid, NTHREADS, SMEM>>>(states, b_ih, b_hh,
                                              d1b, d2b, mw, mb, sw, sb, t);
    }
    final_kernel<<<1, 32>>>(out);
}